// round 1
// baseline (speedup 1.0000x reference)
#include <cuda_runtime.h>
#include <math.h>

// Problem dims (fixed by the reference)
#define BB   16384   // batch (img rows)
#define DD   512     // feature dim
#define NT   4096    // n text
#define HH   1024    // hidden

// ---------------- scratch (device globals; no allocs allowed) ----------------
__device__ float g_txtT [ (size_t)NT * DD ];   // txt_features^T : [NT, DD]
__device__ float g_ht1  [ (size_t)NT * HH ];
__device__ float g_ht2  [ (size_t)NT * HH ];
__device__ float g_ptxt [ (size_t)NT * DD ];   // [NT, DD]
__device__ float g_ptxtT[ (size_t)DD * NT ];   // [DD, NT]
__device__ float g_hi1  [ (size_t)BB * HH ];
__device__ float g_hi2  [ (size_t)BB * HH ];
__device__ float g_pimg [ (size_t)BB * DD ];   // [BB, DD]
__device__ float g_sim  [ (size_t)BB * NT ];   // [BB, NT]  (256 MB)
__device__ float g_picked [ BB ];
__device__ int   g_correct[ BB ];

// ---------------- transpose: in[R,C] -> out[C,R] ----------------
__global__ void transpose_k(const float* __restrict__ in, float* __restrict__ out,
                            int R, int C) {
    __shared__ float t[32][33];
    int c0 = blockIdx.x * 32, r0 = blockIdx.y * 32;
    int c = c0 + threadIdx.x;
    #pragma unroll
    for (int i = 0; i < 32; i += 8) {
        int r = r0 + threadIdx.y + i;
        if (r < R && c < C) t[threadIdx.y + i][threadIdx.x] = in[(size_t)r * C + c];
    }
    __syncthreads();
    int oc = r0 + threadIdx.x;            // output col (= input row)
    #pragma unroll
    for (int i = 0; i < 32; i += 8) {
        int orow = c0 + threadIdx.y + i;  // output row (= input col)
        if (orow < C && oc < R) out[(size_t)orow * R + oc] = t[threadIdx.x][threadIdx.y + i];
    }
}

// ---------------- fp32 SGEMM: C[M,N] = A[M,K] @ B[K,N] (+bias)(+relu) -------
// All dims are multiples of 128 in this problem -> no bounds checks.
#define BM 128
#define BN 128
#define BKT 8
#define TM 8
#define TN 8

template<bool RELU, bool HASBIAS>
__global__ __launch_bounds__(256)
void sgemm(const float* __restrict__ A, const float* __restrict__ B,
           const float* __restrict__ bias, float* __restrict__ C,
           int M, int N, int K) {
    __shared__ float As[BKT][BM];
    __shared__ float Bs[BKT][BN];

    const int tid = threadIdx.x;
    const int bm = blockIdx.y * BM;
    const int bn = blockIdx.x * BN;

    const int tx = tid & 15;          // 0..15  -> col group
    const int ty = tid >> 4;          // 0..15  -> row group

    const int aRow = tid >> 1;        // 0..127
    const int aCol = (tid & 1) * 4;   // 0 or 4
    const int bRow = tid >> 5;        // 0..7
    const int bCol = (tid & 31) * 4;  // 0..124

    const float* Aptr = A + (size_t)(bm + aRow) * K + aCol;
    const float* Bptr = B + (size_t)bRow * N + bn + bCol;

    float acc[TM][TN];
    #pragma unroll
    for (int i = 0; i < TM; i++)
        #pragma unroll
        for (int j = 0; j < TN; j++) acc[i][j] = 0.0f;

    for (int k0 = 0; k0 < K; k0 += BKT) {
        float4 av = *reinterpret_cast<const float4*>(Aptr + k0);
        float4 bv = *reinterpret_cast<const float4*>(Bptr + (size_t)k0 * N);
        As[aCol + 0][aRow] = av.x;
        As[aCol + 1][aRow] = av.y;
        As[aCol + 2][aRow] = av.z;
        As[aCol + 3][aRow] = av.w;
        *reinterpret_cast<float4*>(&Bs[bRow][bCol]) = bv;
        __syncthreads();

        #pragma unroll
        for (int k = 0; k < BKT; k++) {
            float ra[TM], rb[TN];
            #pragma unroll
            for (int i = 0; i < TM; i++) ra[i] = As[k][ty * TM + i];
            #pragma unroll
            for (int j = 0; j < TN; j++) rb[j] = Bs[k][tx * TN + j];
            #pragma unroll
            for (int i = 0; i < TM; i++)
                #pragma unroll
                for (int j = 0; j < TN; j++)
                    acc[i][j] = fmaf(ra[i], rb[j], acc[i][j]);
        }
        __syncthreads();
    }

    #pragma unroll
    for (int i = 0; i < TM; i++) {
        const int row = bm + ty * TM + i;
        #pragma unroll
        for (int j = 0; j < TN; j += 4) {
            const int col = bn + tx * TN + j;
            float4 v;
            v.x = acc[i][j + 0]; v.y = acc[i][j + 1];
            v.z = acc[i][j + 2]; v.w = acc[i][j + 3];
            if (HASBIAS) {
                v.x += bias[col + 0]; v.y += bias[col + 1];
                v.z += bias[col + 2]; v.w += bias[col + 3];
            }
            if (RELU) {
                v.x = fmaxf(v.x, 0.0f); v.y = fmaxf(v.y, 0.0f);
                v.z = fmaxf(v.z, 0.0f); v.w = fmaxf(v.w, 0.0f);
            }
            *reinterpret_cast<float4*>(&C[(size_t)row * N + col]) = v;
        }
    }
}

// ---------------- per-row: normalize (x2), logsumexp, picked, argmax --------
__global__ __launch_bounds__(256)
void row_reduce(const float* __restrict__ sim, const int* __restrict__ target,
                const float* __restrict__ temp_p,
                float* __restrict__ picked, int* __restrict__ correct) {
    const int row = blockIdx.x;
    const float* s = sim + (size_t)row * NT;

    __shared__ float sv[NT];      // 16 KB row cache
    __shared__ float red_f[256];
    __shared__ float red_m[256];
    __shared__ int   red_i[256];

    const int tid = threadIdx.x;

    // pass 1: load, sumsq, argmax
    float sumsq = 0.0f;
    float vmax = -INFINITY; int vidx = 0;
    for (int j = tid; j < NT; j += 256) {
        float v = s[j];
        sv[j] = v;
        sumsq += v * v;
        if (v > vmax) { vmax = v; vidx = j; }
    }
    red_f[tid] = sumsq; red_m[tid] = vmax; red_i[tid] = vidx;
    __syncthreads();
    for (int st = 128; st > 0; st >>= 1) {
        if (tid < st) {
            red_f[tid] += red_f[tid + st];
            float om = red_m[tid + st]; int oi = red_i[tid + st];
            if (om > red_m[tid] || (om == red_m[tid] && oi < red_i[tid])) {
                red_m[tid] = om; red_i[tid] = oi;
            }
        }
        __syncthreads();
    }
    const float c1 = sqrtf(red_f[0]);
    const int   amax = red_i[0];
    const float gmax = red_m[0];
    __syncthreads();

    // pass 2: z = s/c1, second norm
    float ss2 = 0.0f;
    const float inv_c1 = 1.0f / c1;
    for (int j = tid; j < NT; j += 256) {
        float z = sv[j] * inv_c1;
        sv[j] = z;
        ss2 += z * z;
    }
    red_f[tid] = ss2;
    __syncthreads();
    for (int st = 128; st > 0; st >>= 1) {
        if (tid < st) red_f[tid] += red_f[tid + st];
        __syncthreads();
    }
    const float c2 = sqrtf(red_f[0]);
    __syncthreads();

    const float temp = temp_p[0];
    const float invt = 1.0f / (c2 * temp);
    const float lmax = (gmax * inv_c1) * invt;   // max logit (same argmax: positive scale)

    // pass 3: sumexp
    float se = 0.0f;
    for (int j = tid; j < NT; j += 256)
        se += expf(sv[j] * invt - lmax);
    red_f[tid] = se;
    __syncthreads();
    for (int st = 128; st > 0; st >>= 1) {
        if (tid < st) red_f[tid] += red_f[tid + st];
        __syncthreads();
    }

    if (tid == 0) {
        const float lse = lmax + logf(red_f[0]);
        const int t = target[row];
        picked[row]  = sv[t] * invt - lse;
        correct[row] = (amax == t) ? 1 : 0;
    }
}

// ---------------- deterministic final reduce --------------------------------
__global__ __launch_bounds__(1024)
void finalize(const float* __restrict__ picked, const int* __restrict__ correct,
              float* __restrict__ out, int out_size) {
    __shared__ float sp[1024];
    __shared__ int   sc[1024];
    const int tid = threadIdx.x;
    float s = 0.0f; int c = 0;
    for (int i = tid; i < BB; i += 1024) { s += picked[i]; c += correct[i]; }
    sp[tid] = s; sc[tid] = c;
    __syncthreads();
    for (int st = 512; st > 0; st >>= 1) {
        if (tid < st) { sp[tid] += sp[tid + st]; sc[tid] += sc[tid + st]; }
        __syncthreads();
    }
    if (tid == 0) {
        out[0] = -sp[0] / (float)BB;               // loss
        if (out_size >= 2) out[1] = (float)sc[0];  // accuracy count
    }
}

// ---------------- launch ----------------------------------------------------
extern "C" void kernel_launch(void* const* d_in, const int* in_sizes, int n_in,
                              void* d_out, int out_size) {
    const float* img  = (const float*)d_in[0];   // [BB, DD]
    const float* txt  = (const float*)d_in[1];   // [DD, NT]
    const int*   tgt  = (const int*)  d_in[2];   // [BB]
    const float* temp = (const float*)d_in[3];   // scalar
    const float* Wi0 = (const float*)d_in[4];  const float* bi0 = (const float*)d_in[5];
    const float* Wi1 = (const float*)d_in[6];  const float* bi1 = (const float*)d_in[7];
    const float* Wi2 = (const float*)d_in[8];  const float* bi2 = (const float*)d_in[9];
    const float* Wt0 = (const float*)d_in[10]; const float* bt0 = (const float*)d_in[11];
    const float* Wt1 = (const float*)d_in[12]; const float* bt1 = (const float*)d_in[13];
    const float* Wt2 = (const float*)d_in[14]; const float* bt2 = (const float*)d_in[15];
    // d_in[16] = logit_scale : cancels under row L2-normalization, unused.
    float* out = (float*)d_out;

    float *txtT, *ht1, *ht2, *ptxt, *ptxtT, *hi1, *hi2, *pimg, *sim, *picked;
    int *corr;
    cudaGetSymbolAddress((void**)&txtT,  g_txtT);
    cudaGetSymbolAddress((void**)&ht1,   g_ht1);
    cudaGetSymbolAddress((void**)&ht2,   g_ht2);
    cudaGetSymbolAddress((void**)&ptxt,  g_ptxt);
    cudaGetSymbolAddress((void**)&ptxtT, g_ptxtT);
    cudaGetSymbolAddress((void**)&hi1,   g_hi1);
    cudaGetSymbolAddress((void**)&hi2,   g_hi2);
    cudaGetSymbolAddress((void**)&pimg,  g_pimg);
    cudaGetSymbolAddress((void**)&sim,   g_sim);
    cudaGetSymbolAddress((void**)&picked,g_picked);
    cudaGetSymbolAddress((void**)&corr,  g_correct);

    dim3 tb(32, 8);

    // txt branch: x = txt^T  [NT, DD]
    transpose_k<<<dim3(NT/32, DD/32), tb>>>(txt, txtT, DD, NT);
    sgemm<true,  true><<<dim3(HH/BN, NT/BM), 256>>>(txtT, Wt0, bt0, ht1, NT, HH, DD);
    sgemm<true,  true><<<dim3(HH/BN, NT/BM), 256>>>(ht1,  Wt1, bt1, ht2, NT, HH, HH);
    sgemm<false, true><<<dim3(DD/BN, NT/BM), 256>>>(ht2,  Wt2, bt2, ptxt, NT, DD, HH);
    transpose_k<<<dim3(DD/32, NT/32), tb>>>(ptxt, ptxtT, NT, DD);

    // img branch
    sgemm<true,  true><<<dim3(HH/BN, BB/BM), 256>>>(img, Wi0, bi0, hi1, BB, HH, DD);
    sgemm<true,  true><<<dim3(HH/BN, BB/BM), 256>>>(hi1, Wi1, bi1, hi2, BB, HH, HH);
    sgemm<false, true><<<dim3(DD/BN, BB/BM), 256>>>(hi2, Wi2, bi2, pimg, BB, DD, HH);

    // similarity: sim[BB, NT] = pimg @ ptxt^T  (ptxtT is [DD, NT], so NN gemm)
    sgemm<false, false><<<dim3(NT/BN, BB/BM), 256>>>(pimg, ptxtT, nullptr, sim, BB, NT, DD);

    // per-row normalize + log-softmax pick + argmax
    row_reduce<<<BB, 256>>>(sim, tgt, temp, picked, corr);

    // final deterministic reduction
    finalize<<<1, 1024>>>(picked, corr, out, out_size);
}

// round 3
// speedup vs baseline: 1.1691x; 1.1691x over previous
#include <cuda_runtime.h>
#include <math.h>
#include <stdint.h>

// Problem dims (fixed by the reference)
#define BB   16384   // batch (img rows)
#define DD   512     // feature dim
#define NT   4096    // n text
#define HH   1024    // hidden

// ---------------- scratch (device globals; no allocs allowed) ----------------
__device__ float g_txtT [ (size_t)NT * DD ];   // txt_features^T : [NT, DD]
__device__ float g_ht1  [ (size_t)NT * HH ];
__device__ float g_ht2  [ (size_t)NT * HH ];
__device__ float g_ptxt [ (size_t)NT * DD ];   // [NT, DD]
__device__ float g_hi1  [ (size_t)BB * HH ];
__device__ float g_hi2  [ (size_t)BB * HH ];
__device__ float g_pimg [ (size_t)BB * DD ];   // [BB, DD]
__device__ float g_sim  [ (size_t)BB * NT ];   // [BB, NT]  (256 MB)
__device__ float g_picked [ BB ];
__device__ int   g_correct[ BB ];
// transposed weights [fan_out, fan_in]  (K-major B operands)
__device__ float g_Wi0T[ (size_t)HH * DD ];
__device__ float g_Wi1T[ (size_t)HH * HH ];
__device__ float g_Wi2T[ (size_t)DD * HH ];
__device__ float g_Wt0T[ (size_t)HH * DD ];
__device__ float g_Wt1T[ (size_t)HH * HH ];
__device__ float g_Wt2T[ (size_t)DD * HH ];

// ---------------- transpose: in[R,C] -> out[C,R] ----------------
__global__ void transpose_k(const float* __restrict__ in, float* __restrict__ out,
                            int R, int C) {
    __shared__ float t[32][33];
    int c0 = blockIdx.x * 32, r0 = blockIdx.y * 32;
    int c = c0 + threadIdx.x;
    #pragma unroll
    for (int i = 0; i < 32; i += 8) {
        int r = r0 + threadIdx.y + i;
        if (r < R && c < C) t[threadIdx.y + i][threadIdx.x] = in[(size_t)r * C + c];
    }
    __syncthreads();
    int oc = r0 + threadIdx.x;
    #pragma unroll
    for (int i = 0; i < 32; i += 8) {
        int orow = c0 + threadIdx.y + i;
        if (orow < C && oc < R) out[(size_t)orow * R + oc] = t[threadIdx.x][threadIdx.y + i];
    }
}

// ============ mma.sync TF32 GEMM  C[M,N] = A[M,K] * B[N,K]^T  ================
// Block 128x128, BK=32, 8 warps (warp tile 32m x 64n), 3-stage cp.async.
// 3xTF32 split in registers after ldmatrix: D += Ah*Bh + Ah*Bl + Al*Bh.

#define LDA 36                       // floats per smem row (32 + 4 pad)
#define STG_FL (128 * LDA)           // floats per operand stage
#define GEMM_SMEM (3 * 2 * STG_FL * 4)

__device__ __forceinline__ uint32_t smem_u32(const void* p) {
    uint32_t a;
    asm("{ .reg .u64 t; cvta.to.shared.u64 t, %1; cvt.u32.u64 %0, t; }" : "=r"(a) : "l"(p));
    return a;
}
__device__ __forceinline__ void cp16(uint32_t dst, const void* src) {
    asm volatile("cp.async.cg.shared.global [%0], [%1], 16;" :: "r"(dst), "l"(src));
}
__device__ __forceinline__ void ldm_x4(uint32_t& r0, uint32_t& r1, uint32_t& r2,
                                       uint32_t& r3, uint32_t addr) {
    asm volatile("ldmatrix.sync.aligned.m8n8.x4.shared.b16 {%0,%1,%2,%3}, [%4];"
                 : "=r"(r0), "=r"(r1), "=r"(r2), "=r"(r3) : "r"(addr));
}
__device__ __forceinline__ uint32_t cvt_tf32(float v) {
    uint32_t r;
    asm("cvt.rna.tf32.f32 %0, %1;" : "=r"(r) : "f"(v));
    return r;
}
__device__ __forceinline__ void mma8(float* c, uint32_t a0, uint32_t a1, uint32_t a2,
                                     uint32_t a3, uint32_t b0, uint32_t b1) {
    asm volatile(
        "mma.sync.aligned.m16n8k8.row.col.f32.tf32.tf32.f32 "
        "{%0,%1,%2,%3}, {%4,%5,%6,%7}, {%8,%9}, {%0,%1,%2,%3};"
        : "+f"(c[0]), "+f"(c[1]), "+f"(c[2]), "+f"(c[3])
        : "r"(a0), "r"(a1), "r"(a2), "r"(a3), "r"(b0), "r"(b1));
}

__global__ __launch_bounds__(256, 1)
void gemm_mma(const float* __restrict__ A, const float* __restrict__ B,
              const float* __restrict__ bias, float* __restrict__ C,
              int M, int N, int K, int relu)
{
    extern __shared__ float sm[];
    const uint32_t smb = smem_u32(sm);

    const int tid  = threadIdx.x;
    const int lane = tid & 31;
    const int wid  = tid >> 5;
    const int wm   = wid & 3;         // 4 m-groups of 32 rows
    const int wn   = wid >> 2;        // 2 n-groups of 64 cols
    const int bm   = blockIdx.y * 128;
    const int bn   = blockIdx.x * 128;

    const int KI = K >> 5;            // K/32 tiles

    // ---- cp.async stage loader: A[128x32] + B[128x32] fp32 ----
    const int lr = tid >> 3;          // 0..31 row within 32-row pass
    const int lc = (tid & 7) << 2;    // float col (0,4,..,28)
    const float* Abase = A + (size_t)(bm + lr) * K + lc;
    const float* Bbase = B + (size_t)(bn + lr) * K + lc;

    auto load_stage = [&](int buf, int it) {
        const int k0 = it << 5;
        const uint32_t as0 = smb + (uint32_t)(buf * 2 * STG_FL) * 4u;
        const uint32_t bs0 = as0 + (uint32_t)STG_FL * 4u;
        #pragma unroll
        for (int p = 0; p < 4; ++p) {
            const int row = p * 32;
            cp16(as0 + (uint32_t)((lr + row) * LDA + lc) * 4u,
                 Abase + (size_t)row * K + k0);
            cp16(bs0 + (uint32_t)((lr + row) * LDA + lc) * 4u,
                 Bbase + (size_t)row * K + k0);
        }
        asm volatile("cp.async.commit_group;");
    };

    // ---- ldmatrix per-lane address components ----
    // A tiles: row = lane&15 (+ mf*16), k-add = (lane>>4)*4
    const int a_row = (lane & 15);
    const int a_kad = (lane >> 4) << 2;
    // B tiles: row = (lane&7) + (lane>=16 ? 8 : 0) (+ np*16), k-add = ((lane>>3)&1)*4
    const int b_row = (lane & 7) + ((lane >> 4) << 3);
    const int b_kad = ((lane >> 3) & 1) << 2;

    float acc[2][8][4];
    #pragma unroll
    for (int i = 0; i < 2; ++i)
        #pragma unroll
        for (int j = 0; j < 8; ++j)
            #pragma unroll
            for (int q = 0; q < 4; ++q) acc[i][j][q] = 0.0f;

    // prologue: fill 3 stages
    load_stage(0, 0);
    load_stage(1, 1);
    load_stage(2, 2);

    for (int it = 0; it < KI; ++it) {
        asm volatile("cp.async.wait_group 2;");
        __syncthreads();

        const int buf = it - (it / 3) * 3;
        const uint32_t as0 = smb + (uint32_t)(buf * 2 * STG_FL) * 4u;
        const uint32_t bs0 = as0 + (uint32_t)STG_FL * 4u;
        const uint32_t a_lane = as0 + (uint32_t)((wm * 32 + a_row) * LDA + a_kad) * 4u;
        const uint32_t b_lane = bs0 + (uint32_t)((wn * 64 + b_row) * LDA + b_kad) * 4u;

        #pragma unroll
        for (int s = 0; s < 4; ++s) {
            const uint32_t koff = (uint32_t)(s << 5);   // s*8 floats = 32B

            // ---- load + split A fragments (2 m-frags) ----
            uint32_t ah[2][4], al[2][4];
            #pragma unroll
            for (int mf = 0; mf < 2; ++mf) {
                uint32_t r0, r1, r2, r3;
                ldm_x4(r0, r1, r2, r3, a_lane + (uint32_t)(mf * 16 * LDA) * 4u + koff);
                float f0 = __uint_as_float(r0), f1 = __uint_as_float(r1);
                float f2 = __uint_as_float(r2), f3 = __uint_as_float(r3);
                ah[mf][0] = cvt_tf32(f0); al[mf][0] = cvt_tf32(f0 - __uint_as_float(ah[mf][0]));
                ah[mf][1] = cvt_tf32(f1); al[mf][1] = cvt_tf32(f1 - __uint_as_float(ah[mf][1]));
                ah[mf][2] = cvt_tf32(f2); al[mf][2] = cvt_tf32(f2 - __uint_as_float(ah[mf][2]));
                ah[mf][3] = cvt_tf32(f3); al[mf][3] = cvt_tf32(f3 - __uint_as_float(ah[mf][3]));
            }
            // ---- load + split B fragments (8 n-frags via 4 x4-ldmatrix) ----
            uint32_t bh[8][2], bl[8][2];
            #pragma unroll
            for (int np = 0; np < 4; ++np) {
                uint32_t r0, r1, r2, r3;
                ldm_x4(r0, r1, r2, r3, b_lane + (uint32_t)(np * 16 * LDA) * 4u + koff);
                float f0 = __uint_as_float(r0), f1 = __uint_as_float(r1);
                float f2 = __uint_as_float(r2), f3 = __uint_as_float(r3);
                const int nf = np * 2;
                bh[nf][0]     = cvt_tf32(f0); bl[nf][0]     = cvt_tf32(f0 - __uint_as_float(bh[nf][0]));
                bh[nf][1]     = cvt_tf32(f1); bl[nf][1]     = cvt_tf32(f1 - __uint_as_float(bh[nf][1]));
                bh[nf + 1][0] = cvt_tf32(f2); bl[nf + 1][0] = cvt_tf32(f2 - __uint_as_float(bh[nf + 1][0]));
                bh[nf + 1][1] = cvt_tf32(f3); bl[nf + 1][1] = cvt_tf32(f3 - __uint_as_float(bh[nf + 1][1]));
            }
            // ---- 3xTF32 MMAs ----
            #pragma unroll
            for (int mf = 0; mf < 2; ++mf)
                #pragma unroll
                for (int nf = 0; nf < 8; ++nf) {
                    float* c = acc[mf][nf];
                    mma8(c, ah[mf][0], ah[mf][1], ah[mf][2], ah[mf][3], bh[nf][0], bh[nf][1]);
                    mma8(c, ah[mf][0], ah[mf][1], ah[mf][2], ah[mf][3], bl[nf][0], bl[nf][1]);
                    mma8(c, al[mf][0], al[mf][1], al[mf][2], al[mf][3], bh[nf][0], bh[nf][1]);
                }
        }

        __syncthreads();
        const int nt = it + 3;
        if (nt < KI) load_stage(buf, nt);
        else         asm volatile("cp.async.commit_group;");
    }

    // ---- epilogue ----
    const bool hb = (bias != nullptr);
    #pragma unroll
    for (int mf = 0; mf < 2; ++mf) {
        const int r0 = bm + wm * 32 + mf * 16 + (lane >> 2);
        #pragma unroll
        for (int nf = 0; nf < 8; ++nf) {
            const int col = bn + wn * 64 + nf * 8 + ((lane & 3) << 1);
            float2 v0, v1;
            v0.x = acc[mf][nf][0]; v0.y = acc[mf][nf][1];
            v1.x = acc[mf][nf][2]; v1.y = acc[mf][nf][3];
            if (hb) {
                const float bx = bias[col], by = bias[col + 1];
                v0.x += bx; v0.y += by; v1.x += bx; v1.y += by;
            }
            if (relu) {
                v0.x = fmaxf(v0.x, 0.f); v0.y = fmaxf(v0.y, 0.f);
                v1.x = fmaxf(v1.x, 0.f); v1.y = fmaxf(v1.y, 0.f);
            }
            *reinterpret_cast<float2*>(C + (size_t)r0 * N + col)       = v0;
            *reinterpret_cast<float2*>(C + (size_t)(r0 + 8) * N + col) = v1;
        }
    }
}

// ---------------- per-row: normalize (x2), logsumexp, picked, argmax --------
__global__ __launch_bounds__(256)
void row_reduce(const float* __restrict__ sim, const int* __restrict__ target,
                const float* __restrict__ temp_p,
                float* __restrict__ picked, int* __restrict__ correct) {
    const int row = blockIdx.x;
    const float* s = sim + (size_t)row * NT;

    __shared__ float sv[NT];
    __shared__ float red_f[256];
    __shared__ float red_m[256];
    __shared__ int   red_i[256];

    const int tid = threadIdx.x;

    float sumsq = 0.0f;
    float vmax = -INFINITY; int vidx = 0;
    for (int j = tid; j < NT; j += 256) {
        float v = s[j];
        sv[j] = v;
        sumsq += v * v;
        if (v > vmax) { vmax = v; vidx = j; }
    }
    red_f[tid] = sumsq; red_m[tid] = vmax; red_i[tid] = vidx;
    __syncthreads();
    for (int st = 128; st > 0; st >>= 1) {
        if (tid < st) {
            red_f[tid] += red_f[tid + st];
            float om = red_m[tid + st]; int oi = red_i[tid + st];
            if (om > red_m[tid] || (om == red_m[tid] && oi < red_i[tid])) {
                red_m[tid] = om; red_i[tid] = oi;
            }
        }
        __syncthreads();
    }
    const float c1 = sqrtf(red_f[0]);
    const int   amax = red_i[0];
    const float gmax = red_m[0];
    __syncthreads();

    float ss2 = 0.0f;
    const float inv_c1 = 1.0f / c1;
    for (int j = tid; j < NT; j += 256) {
        float z = sv[j] * inv_c1;
        sv[j] = z;
        ss2 += z * z;
    }
    red_f[tid] = ss2;
    __syncthreads();
    for (int st = 128; st > 0; st >>= 1) {
        if (tid < st) red_f[tid] += red_f[tid + st];
        __syncthreads();
    }
    const float c2 = sqrtf(red_f[0]);
    __syncthreads();

    const float temp = temp_p[0];
    const float invt = 1.0f / (c2 * temp);
    const float lmax = (gmax * inv_c1) * invt;

    float se = 0.0f;
    for (int j = tid; j < NT; j += 256)
        se += expf(sv[j] * invt - lmax);
    red_f[tid] = se;
    __syncthreads();
    for (int st = 128; st > 0; st >>= 1) {
        if (tid < st) red_f[tid] += red_f[tid + st];
        __syncthreads();
    }

    if (tid == 0) {
        const float lse = lmax + logf(red_f[0]);
        const int t = target[row];
        picked[row]  = sv[t] * invt - lse;
        correct[row] = (amax == t) ? 1 : 0;
    }
}

// ---------------- deterministic final reduce --------------------------------
__global__ __launch_bounds__(1024)
void finalize(const float* __restrict__ picked, const int* __restrict__ correct,
              float* __restrict__ out, int out_size) {
    __shared__ float sp[1024];
    __shared__ int   sc[1024];
    const int tid = threadIdx.x;
    float s = 0.0f; int c = 0;
    for (int i = tid; i < BB; i += 1024) { s += picked[i]; c += correct[i]; }
    sp[tid] = s; sc[tid] = c;
    __syncthreads();
    for (int st = 512; st > 0; st >>= 1) {
        if (tid < st) { sp[tid] += sp[tid + st]; sc[tid] += sc[tid + st]; }
        __syncthreads();
    }
    if (tid == 0) {
        out[0] = -sp[0] / (float)BB;
        if (out_size >= 2) out[1] = (float)sc[0];
    }
}

// ---------------- launch ----------------------------------------------------
extern "C" void kernel_launch(void* const* d_in, const int* in_sizes, int n_in,
                              void* d_out, int out_size) {
    const float* img  = (const float*)d_in[0];
    const float* txt  = (const float*)d_in[1];
    const int*   tgt  = (const int*)  d_in[2];
    const float* temp = (const float*)d_in[3];
    const float* Wi0 = (const float*)d_in[4];  const float* bi0 = (const float*)d_in[5];
    const float* Wi1 = (const float*)d_in[6];  const float* bi1 = (const float*)d_in[7];
    const float* Wi2 = (const float*)d_in[8];  const float* bi2 = (const float*)d_in[9];
    const float* Wt0 = (const float*)d_in[10]; const float* bt0 = (const float*)d_in[11];
    const float* Wt1 = (const float*)d_in[12]; const float* bt1 = (const float*)d_in[13];
    const float* Wt2 = (const float*)d_in[14]; const float* bt2 = (const float*)d_in[15];
    // d_in[16] = logit_scale : cancels under row L2-normalization, unused.
    float* out = (float*)d_out;

    float *txtT, *ht1, *ht2, *ptxt, *hi1, *hi2, *pimg, *sim, *picked;
    float *Wi0T, *Wi1T, *Wi2T, *Wt0T, *Wt1T, *Wt2T;
    int *corr;
    cudaGetSymbolAddress((void**)&txtT,  g_txtT);
    cudaGetSymbolAddress((void**)&ht1,   g_ht1);
    cudaGetSymbolAddress((void**)&ht2,   g_ht2);
    cudaGetSymbolAddress((void**)&ptxt,  g_ptxt);
    cudaGetSymbolAddress((void**)&hi1,   g_hi1);
    cudaGetSymbolAddress((void**)&hi2,   g_hi2);
    cudaGetSymbolAddress((void**)&pimg,  g_pimg);
    cudaGetSymbolAddress((void**)&sim,   g_sim);
    cudaGetSymbolAddress((void**)&picked,g_picked);
    cudaGetSymbolAddress((void**)&corr,  g_correct);
    cudaGetSymbolAddress((void**)&Wi0T,  g_Wi0T);
    cudaGetSymbolAddress((void**)&Wi1T,  g_Wi1T);
    cudaGetSymbolAddress((void**)&Wi2T,  g_Wi2T);
    cudaGetSymbolAddress((void**)&Wt0T,  g_Wt0T);
    cudaGetSymbolAddress((void**)&Wt1T,  g_Wt1T);
    cudaGetSymbolAddress((void**)&Wt2T,  g_Wt2T);

    cudaFuncSetAttribute(gemm_mma, cudaFuncAttributeMaxDynamicSharedMemorySize, GEMM_SMEM);

    dim3 tb(32, 8);

    // transposes: txt features + all weights (to [N,K] K-major B operands)
    transpose_k<<<dim3(NT/32, DD/32), tb>>>(txt, txtT, DD, NT);
    transpose_k<<<dim3(HH/32, DD/32), tb>>>(Wi0, Wi0T, DD, HH);
    transpose_k<<<dim3(HH/32, HH/32), tb>>>(Wi1, Wi1T, HH, HH);
    transpose_k<<<dim3(DD/32, HH/32), tb>>>(Wi2, Wi2T, HH, DD);
    transpose_k<<<dim3(HH/32, DD/32), tb>>>(Wt0, Wt0T, DD, HH);
    transpose_k<<<dim3(HH/32, HH/32), tb>>>(Wt1, Wt1T, HH, HH);
    transpose_k<<<dim3(DD/32, HH/32), tb>>>(Wt2, Wt2T, HH, DD);

    // txt MLP:  [NT,DD] -> [NT,HH] -> [NT,HH] -> [NT,DD]
    gemm_mma<<<dim3(HH/128, NT/128), 256, GEMM_SMEM>>>(txtT, Wt0T, bt0, ht1, NT, HH, DD, 1);
    gemm_mma<<<dim3(HH/128, NT/128), 256, GEMM_SMEM>>>(ht1,  Wt1T, bt1, ht2, NT, HH, HH, 1);
    gemm_mma<<<dim3(DD/128, NT/128), 256, GEMM_SMEM>>>(ht2,  Wt2T, bt2, ptxt, NT, DD, HH, 0);

    // img MLP:  [BB,DD] -> [BB,HH] -> [BB,HH] -> [BB,DD]
    gemm_mma<<<dim3(HH/128, BB/128), 256, GEMM_SMEM>>>(img, Wi0T, bi0, hi1, BB, HH, DD, 1);
    gemm_mma<<<dim3(HH/128, BB/128), 256, GEMM_SMEM>>>(hi1, Wi1T, bi1, hi2, BB, HH, HH, 1);
    gemm_mma<<<dim3(DD/128, BB/128), 256, GEMM_SMEM>>>(hi2, Wi2T, bi2, pimg, BB, DD, HH, 0);

    // similarity: sim[BB, NT] = pimg @ ptxt^T  (ptxt is [NT, DD] K-major already)
    gemm_mma<<<dim3(NT/128, BB/128), 256, GEMM_SMEM>>>(pimg, ptxt, nullptr, sim, BB, NT, DD, 0);

    // per-row normalize + log-softmax pick + argmax
    row_reduce<<<BB, 256>>>(sim, tgt, temp, picked, corr);

    // final deterministic reduction
    finalize<<<1, 1024>>>(picked, corr, out, out_size);
}

// round 4
// speedup vs baseline: 1.4726x; 1.2596x over previous
#include <cuda_runtime.h>
#include <math.h>
#include <stdint.h>

// Problem dims (fixed by the reference)
#define BB   16384   // batch (img rows)
#define DD   512     // feature dim
#define NT   4096    // n text
#define HH   1024    // hidden

// ---------------- scratch (device globals; no allocs allowed) ----------------
// hi/lo tf32-split operand arrays (stored as float bit patterns)
__device__ float g_img_h [ (size_t)BB * DD ], g_img_l [ (size_t)BB * DD ];
__device__ float g_txtT_h[ (size_t)NT * DD ], g_txtT_l[ (size_t)NT * DD ];
__device__ float g_ht1_h [ (size_t)NT * HH ], g_ht1_l [ (size_t)NT * HH ];
__device__ float g_ht2_h [ (size_t)NT * HH ], g_ht2_l [ (size_t)NT * HH ];
__device__ float g_ptxt_h[ (size_t)NT * DD ], g_ptxt_l[ (size_t)NT * DD ];
__device__ float g_hi1_h [ (size_t)BB * HH ], g_hi1_l [ (size_t)BB * HH ];
__device__ float g_hi2_h [ (size_t)BB * HH ], g_hi2_l [ (size_t)BB * HH ];
__device__ float g_pimg_h[ (size_t)BB * DD ], g_pimg_l[ (size_t)BB * DD ];
__device__ float g_Wi0T_h[ (size_t)HH * DD ], g_Wi0T_l[ (size_t)HH * DD ];
__device__ float g_Wi1T_h[ (size_t)HH * HH ], g_Wi1T_l[ (size_t)HH * HH ];
__device__ float g_Wi2T_h[ (size_t)DD * HH ], g_Wi2T_l[ (size_t)DD * HH ];
__device__ float g_Wt0T_h[ (size_t)HH * DD ], g_Wt0T_l[ (size_t)HH * DD ];
__device__ float g_Wt1T_h[ (size_t)HH * HH ], g_Wt1T_l[ (size_t)HH * HH ];
__device__ float g_Wt2T_h[ (size_t)DD * HH ], g_Wt2T_l[ (size_t)DD * HH ];
__device__ float g_sim  [ (size_t)BB * NT ];   // [BB, NT]  (256 MB)
__device__ float g_picked [ BB ];
__device__ int   g_correct[ BB ];

__device__ __forceinline__ uint32_t cvt_tf32(float v) {
    uint32_t r;
    asm("cvt.rna.tf32.f32 %0, %1;" : "=r"(r) : "f"(v));
    return r;
}
__device__ __forceinline__ void split1(float v, float& h, float& l) {
    uint32_t hb = cvt_tf32(v);
    h = __uint_as_float(hb);
    l = __uint_as_float(cvt_tf32(v - h));
}

// ---------------- elementwise split: in -> (hi, lo) ----------------
__global__ __launch_bounds__(256)
void split_k(const float* __restrict__ in, float* __restrict__ hi,
             float* __restrict__ lo, size_t n4) {
    size_t i = (size_t)blockIdx.x * 256 + threadIdx.x;
    size_t stride = (size_t)gridDim.x * 256;
    for (; i < n4; i += stride) {
        float4 v = reinterpret_cast<const float4*>(in)[i];
        float4 h, l;
        split1(v.x, h.x, l.x); split1(v.y, h.y, l.y);
        split1(v.z, h.z, l.z); split1(v.w, h.w, l.w);
        reinterpret_cast<float4*>(hi)[i] = h;
        reinterpret_cast<float4*>(lo)[i] = l;
    }
}

// ---------------- transpose + split: in[R,C] -> hi/lo[C,R] ----------------
__global__ void transpose_split_k(const float* __restrict__ in,
                                  float* __restrict__ hi, float* __restrict__ lo,
                                  int R, int C) {
    __shared__ float t[32][33];
    int c0 = blockIdx.x * 32, r0 = blockIdx.y * 32;
    int c = c0 + threadIdx.x;
    #pragma unroll
    for (int i = 0; i < 32; i += 8) {
        int r = r0 + threadIdx.y + i;
        if (r < R && c < C) t[threadIdx.y + i][threadIdx.x] = in[(size_t)r * C + c];
    }
    __syncthreads();
    int oc = r0 + threadIdx.x;
    #pragma unroll
    for (int i = 0; i < 32; i += 8) {
        int orow = c0 + threadIdx.y + i;
        if (orow < C && oc < R) {
            float v = t[threadIdx.x][threadIdx.y + i];
            float h, l; split1(v, h, l);
            hi[(size_t)orow * R + oc] = h;
            lo[(size_t)orow * R + oc] = l;
        }
    }
}

// ============ mma.sync TF32 GEMM  C[M,N] = A[M,K] * B[N,K]^T  ================
// Block 128x256, BK=32, 16 warps (warp tile 32m x 64n), 2-stage cp.async.
// Operands pre-split (hi/lo tf32). Inner loop: ldmatrix + mma only.

#define LDA 36                        // floats per smem row (32 + 4 pad)
#define A_FL (128 * LDA)
#define B_FL (256 * LDA)
#define STAGE_FL (2 * A_FL + 2 * B_FL)
#define GEMM_SMEM (2 * STAGE_FL * 4)  // 221184 B

__device__ __forceinline__ uint32_t smem_u32(const void* p) {
    uint32_t a;
    asm("{ .reg .u64 t; cvta.to.shared.u64 t, %1; cvt.u32.u64 %0, t; }" : "=r"(a) : "l"(p));
    return a;
}
__device__ __forceinline__ void cp16(uint32_t dst, const void* src) {
    asm volatile("cp.async.cg.shared.global [%0], [%1], 16;" :: "r"(dst), "l"(src));
}
__device__ __forceinline__ void ldm_x4(uint32_t& r0, uint32_t& r1, uint32_t& r2,
                                       uint32_t& r3, uint32_t addr) {
    asm volatile("ldmatrix.sync.aligned.m8n8.x4.shared.b16 {%0,%1,%2,%3}, [%4];"
                 : "=r"(r0), "=r"(r1), "=r"(r2), "=r"(r3) : "r"(addr));
}
__device__ __forceinline__ void mma8(float* c, const uint32_t* a, uint32_t b0, uint32_t b1) {
    asm volatile(
        "mma.sync.aligned.m16n8k8.row.col.f32.tf32.tf32.f32 "
        "{%0,%1,%2,%3}, {%4,%5,%6,%7}, {%8,%9}, {%0,%1,%2,%3};"
        : "+f"(c[0]), "+f"(c[1]), "+f"(c[2]), "+f"(c[3])
        : "r"(a[0]), "r"(a[1]), "r"(a[2]), "r"(a[3]), "r"(b0), "r"(b1));
}

__global__ __launch_bounds__(512, 1)
void gemm_mma(const float* __restrict__ Ah, const float* __restrict__ Al,
              const float* __restrict__ Bh, const float* __restrict__ Bl,
              const float* __restrict__ bias,
              float* __restrict__ C,                      // plain output (may be null)
              float* __restrict__ Ch, float* __restrict__ Cl,  // split output (may be null)
              int M, int N, int K, int relu)
{
    extern __shared__ float sm[];
    const uint32_t smb = smem_u32(sm);

    const int tid  = threadIdx.x;
    const int lane = tid & 31;
    const int wid  = tid >> 5;        // 0..15
    const int wm   = wid & 3;         // 4 m-groups of 32 rows
    const int wn   = wid >> 2;        // 4 n-groups of 64 cols
    const int bm   = blockIdx.y * 128;
    const int bn   = blockIdx.x * 256;

    const int KI = K >> 5;            // K/32 tiles

    // ---- cp.async stage loader ----
    const int lr = tid >> 3;          // 0..63
    const int lc = (tid & 7) << 2;    // float col 0,4,..,28

    auto load_stage = [&](int buf, int it) {
        const int k0 = it << 5;
        const uint32_t st = smb + (uint32_t)(buf * STAGE_FL) * 4u;
        const uint32_t ah_s = st;
        const uint32_t al_s = st + (uint32_t)A_FL * 4u;
        const uint32_t bh_s = st + (uint32_t)(2 * A_FL) * 4u;
        const uint32_t bl_s = st + (uint32_t)(2 * A_FL + B_FL) * 4u;
        #pragma unroll
        for (int p = 0; p < 2; ++p) {                 // A: 128 rows
            const int row = lr + p * 64;
            const size_t g = (size_t)(bm + row) * K + k0 + lc;
            const uint32_t s = (uint32_t)(row * LDA + lc) * 4u;
            cp16(ah_s + s, Ah + g);
            cp16(al_s + s, Al + g);
        }
        #pragma unroll
        for (int p = 0; p < 4; ++p) {                 // B: 256 rows
            const int row = lr + p * 64;
            const size_t g = (size_t)(bn + row) * K + k0 + lc;
            const uint32_t s = (uint32_t)(row * LDA + lc) * 4u;
            cp16(bh_s + s, Bh + g);
            cp16(bl_s + s, Bl + g);
        }
        asm volatile("cp.async.commit_group;");
    };

    // ---- ldmatrix per-lane address components ----
    const int a_row = (lane & 15);
    const int a_kad = (lane >> 4) << 2;
    const int b_row = (lane & 7) + ((lane >> 4) << 3);
    const int b_kad = ((lane >> 3) & 1) << 2;

    float acc[2][8][4];
    #pragma unroll
    for (int i = 0; i < 2; ++i)
        #pragma unroll
        for (int j = 0; j < 8; ++j)
            #pragma unroll
            for (int q = 0; q < 4; ++q) acc[i][j][q] = 0.0f;

    load_stage(0, 0);
    load_stage(1, 1);

    for (int it = 0; it < KI; ++it) {
        asm volatile("cp.async.wait_group 1;");
        __syncthreads();

        const int buf = it & 1;
        const uint32_t st = smb + (uint32_t)(buf * STAGE_FL) * 4u;
        const uint32_t a_h = st + (uint32_t)((wm * 32 + a_row) * LDA + a_kad) * 4u;
        const uint32_t a_l = a_h + (uint32_t)A_FL * 4u;
        const uint32_t b_h = st + (uint32_t)(2 * A_FL) * 4u
                           + (uint32_t)((wn * 64 + b_row) * LDA + b_kad) * 4u;
        const uint32_t b_l = b_h + (uint32_t)B_FL * 4u;

        #pragma unroll
        for (int s = 0; s < 4; ++s) {
            const uint32_t koff = (uint32_t)(s << 5);   // s*8 floats = 32B

            uint32_t ah[2][4], al[2][4];
            #pragma unroll
            for (int mf = 0; mf < 2; ++mf) {
                const uint32_t moff = (uint32_t)(mf * 16 * LDA) * 4u + koff;
                ldm_x4(ah[mf][0], ah[mf][1], ah[mf][2], ah[mf][3], a_h + moff);
                ldm_x4(al[mf][0], al[mf][1], al[mf][2], al[mf][3], a_l + moff);
            }
            uint32_t bh[8][2], bl[8][2];
            #pragma unroll
            for (int np = 0; np < 4; ++np) {
                const uint32_t noff = (uint32_t)(np * 16 * LDA) * 4u + koff;
                uint32_t r0, r1, r2, r3;
                ldm_x4(r0, r1, r2, r3, b_h + noff);
                bh[np*2][0] = r0; bh[np*2][1] = r1; bh[np*2+1][0] = r2; bh[np*2+1][1] = r3;
                ldm_x4(r0, r1, r2, r3, b_l + noff);
                bl[np*2][0] = r0; bl[np*2][1] = r1; bl[np*2+1][0] = r2; bl[np*2+1][1] = r3;
            }
            #pragma unroll
            for (int mf = 0; mf < 2; ++mf)
                #pragma unroll
                for (int nf = 0; nf < 8; ++nf) {
                    float* c = acc[mf][nf];
                    mma8(c, ah[mf], bh[nf][0], bh[nf][1]);
                    mma8(c, ah[mf], bl[nf][0], bl[nf][1]);
                    mma8(c, al[mf], bh[nf][0], bh[nf][1]);
                }
        }

        __syncthreads();
        const int nt = it + 2;
        if (nt < KI) load_stage(buf, nt);
        else         asm volatile("cp.async.commit_group;");
    }

    // ---- epilogue ----
    const bool hb = (bias != nullptr);
    const bool dosplit = (Ch != nullptr);
    #pragma unroll
    for (int mf = 0; mf < 2; ++mf) {
        const int r0 = bm + wm * 32 + mf * 16 + (lane >> 2);
        #pragma unroll
        for (int nf = 0; nf < 8; ++nf) {
            const int col = bn + wn * 64 + nf * 8 + ((lane & 3) << 1);
            float v[4];
            v[0] = acc[mf][nf][0]; v[1] = acc[mf][nf][1];
            v[2] = acc[mf][nf][2]; v[3] = acc[mf][nf][3];
            if (hb) {
                const float bx = bias[col], by = bias[col + 1];
                v[0] += bx; v[1] += by; v[2] += bx; v[3] += by;
            }
            if (relu) {
                v[0] = fmaxf(v[0], 0.f); v[1] = fmaxf(v[1], 0.f);
                v[2] = fmaxf(v[2], 0.f); v[3] = fmaxf(v[3], 0.f);
            }
            const size_t o0 = (size_t)r0 * N + col;
            const size_t o1 = (size_t)(r0 + 8) * N + col;
            if (dosplit) {
                float h[4], l[4];
                split1(v[0], h[0], l[0]); split1(v[1], h[1], l[1]);
                split1(v[2], h[2], l[2]); split1(v[3], h[3], l[3]);
                *reinterpret_cast<float2*>(Ch + o0) = make_float2(h[0], h[1]);
                *reinterpret_cast<float2*>(Cl + o0) = make_float2(l[0], l[1]);
                *reinterpret_cast<float2*>(Ch + o1) = make_float2(h[2], h[3]);
                *reinterpret_cast<float2*>(Cl + o1) = make_float2(l[2], l[3]);
            } else {
                *reinterpret_cast<float2*>(C + o0) = make_float2(v[0], v[1]);
                *reinterpret_cast<float2*>(C + o1) = make_float2(v[2], v[3]);
            }
        }
    }
}

// ---------------- per-row: normalize (x2), logsumexp, picked, argmax --------
__global__ __launch_bounds__(256)
void row_reduce(const float* __restrict__ sim, const int* __restrict__ target,
                const float* __restrict__ temp_p,
                float* __restrict__ picked, int* __restrict__ correct) {
    const int row = blockIdx.x;
    const float* s = sim + (size_t)row * NT;

    __shared__ float sv[NT];
    __shared__ float red_f[256];
    __shared__ float red_m[256];
    __shared__ int   red_i[256];

    const int tid = threadIdx.x;

    float sumsq = 0.0f;
    float vmax = -INFINITY; int vidx = 0;
    for (int j = tid; j < NT; j += 256) {
        float v = s[j];
        sv[j] = v;
        sumsq += v * v;
        if (v > vmax) { vmax = v; vidx = j; }
    }
    red_f[tid] = sumsq; red_m[tid] = vmax; red_i[tid] = vidx;
    __syncthreads();
    for (int st = 128; st > 0; st >>= 1) {
        if (tid < st) {
            red_f[tid] += red_f[tid + st];
            float om = red_m[tid + st]; int oi = red_i[tid + st];
            if (om > red_m[tid] || (om == red_m[tid] && oi < red_i[tid])) {
                red_m[tid] = om; red_i[tid] = oi;
            }
        }
        __syncthreads();
    }
    const float c1 = sqrtf(red_f[0]);
    const int   amax = red_i[0];
    const float gmax = red_m[0];
    __syncthreads();

    float ss2 = 0.0f;
    const float inv_c1 = 1.0f / c1;
    for (int j = tid; j < NT; j += 256) {
        float z = sv[j] * inv_c1;
        sv[j] = z;
        ss2 += z * z;
    }
    red_f[tid] = ss2;
    __syncthreads();
    for (int st = 128; st > 0; st >>= 1) {
        if (tid < st) red_f[tid] += red_f[tid + st];
        __syncthreads();
    }
    const float c2 = sqrtf(red_f[0]);
    __syncthreads();

    const float temp = temp_p[0];
    const float invt = 1.0f / (c2 * temp);
    const float lmax = (gmax * inv_c1) * invt;

    float se = 0.0f;
    for (int j = tid; j < NT; j += 256)
        se += expf(sv[j] * invt - lmax);
    red_f[tid] = se;
    __syncthreads();
    for (int st = 128; st > 0; st >>= 1) {
        if (tid < st) red_f[tid] += red_f[tid + st];
        __syncthreads();
    }

    if (tid == 0) {
        const float lse = lmax + logf(red_f[0]);
        const int t = target[row];
        picked[row]  = sv[t] * invt - lse;
        correct[row] = (amax == t) ? 1 : 0;
    }
}

// ---------------- deterministic final reduce --------------------------------
__global__ __launch_bounds__(1024)
void finalize(const float* __restrict__ picked, const int* __restrict__ correct,
              float* __restrict__ out, int out_size) {
    __shared__ float sp[1024];
    __shared__ int   sc[1024];
    const int tid = threadIdx.x;
    float s = 0.0f; int c = 0;
    for (int i = tid; i < BB; i += 1024) { s += picked[i]; c += correct[i]; }
    sp[tid] = s; sc[tid] = c;
    __syncthreads();
    for (int st = 512; st > 0; st >>= 1) {
        if (tid < st) { sp[tid] += sp[tid + st]; sc[tid] += sc[tid + st]; }
        __syncthreads();
    }
    if (tid == 0) {
        out[0] = -sp[0] / (float)BB;
        if (out_size >= 2) out[1] = (float)sc[0];
    }
}

// ---------------- launch ----------------------------------------------------
#define SYM(v, s) cudaGetSymbolAddress((void**)&v, s)

extern "C" void kernel_launch(void* const* d_in, const int* in_sizes, int n_in,
                              void* d_out, int out_size) {
    const float* img  = (const float*)d_in[0];
    const float* txt  = (const float*)d_in[1];
    const int*   tgt  = (const int*)  d_in[2];
    const float* temp = (const float*)d_in[3];
    const float* Wi0 = (const float*)d_in[4];  const float* bi0 = (const float*)d_in[5];
    const float* Wi1 = (const float*)d_in[6];  const float* bi1 = (const float*)d_in[7];
    const float* Wi2 = (const float*)d_in[8];  const float* bi2 = (const float*)d_in[9];
    const float* Wt0 = (const float*)d_in[10]; const float* bt0 = (const float*)d_in[11];
    const float* Wt1 = (const float*)d_in[12]; const float* bt1 = (const float*)d_in[13];
    const float* Wt2 = (const float*)d_in[14]; const float* bt2 = (const float*)d_in[15];
    // d_in[16] = logit_scale : cancels under row L2-normalization, unused.
    float* out = (float*)d_out;

    float *img_h, *img_l, *txtT_h, *txtT_l, *ht1_h, *ht1_l, *ht2_h, *ht2_l;
    float *ptxt_h, *ptxt_l, *hi1_h, *hi1_l, *hi2_h, *hi2_l, *pimg_h, *pimg_l;
    float *Wi0T_h, *Wi0T_l, *Wi1T_h, *Wi1T_l, *Wi2T_h, *Wi2T_l;
    float *Wt0T_h, *Wt0T_l, *Wt1T_h, *Wt1T_l, *Wt2T_h, *Wt2T_l;
    float *sim, *picked; int *corr;
    SYM(img_h,  g_img_h);  SYM(img_l,  g_img_l);
    SYM(txtT_h, g_txtT_h); SYM(txtT_l, g_txtT_l);
    SYM(ht1_h,  g_ht1_h);  SYM(ht1_l,  g_ht1_l);
    SYM(ht2_h,  g_ht2_h);  SYM(ht2_l,  g_ht2_l);
    SYM(ptxt_h, g_ptxt_h); SYM(ptxt_l, g_ptxt_l);
    SYM(hi1_h,  g_hi1_h);  SYM(hi1_l,  g_hi1_l);
    SYM(hi2_h,  g_hi2_h);  SYM(hi2_l,  g_hi2_l);
    SYM(pimg_h, g_pimg_h); SYM(pimg_l, g_pimg_l);
    SYM(Wi0T_h, g_Wi0T_h); SYM(Wi0T_l, g_Wi0T_l);
    SYM(Wi1T_h, g_Wi1T_h); SYM(Wi1T_l, g_Wi1T_l);
    SYM(Wi2T_h, g_Wi2T_h); SYM(Wi2T_l, g_Wi2T_l);
    SYM(Wt0T_h, g_Wt0T_h); SYM(Wt0T_l, g_Wt0T_l);
    SYM(Wt1T_h, g_Wt1T_h); SYM(Wt1T_l, g_Wt1T_l);
    SYM(Wt2T_h, g_Wt2T_h); SYM(Wt2T_l, g_Wt2T_l);
    SYM(sim, g_sim); SYM(picked, g_picked); SYM(corr, g_correct);

    cudaFuncSetAttribute(gemm_mma, cudaFuncAttributeMaxDynamicSharedMemorySize, GEMM_SMEM);

    dim3 tb(32, 8);

    // input splits (img) and transpose+splits (txt features + 6 weights)
    split_k<<<256, 256>>>(img, img_h, img_l, (size_t)BB * DD / 4);
    transpose_split_k<<<dim3(NT/32, DD/32), tb>>>(txt, txtT_h, txtT_l, DD, NT);
    transpose_split_k<<<dim3(HH/32, DD/32), tb>>>(Wi0, Wi0T_h, Wi0T_l, DD, HH);
    transpose_split_k<<<dim3(HH/32, HH/32), tb>>>(Wi1, Wi1T_h, Wi1T_l, HH, HH);
    transpose_split_k<<<dim3(DD/32, HH/32), tb>>>(Wi2, Wi2T_h, Wi2T_l, HH, DD);
    transpose_split_k<<<dim3(HH/32, DD/32), tb>>>(Wt0, Wt0T_h, Wt0T_l, DD, HH);
    transpose_split_k<<<dim3(HH/32, HH/32), tb>>>(Wt1, Wt1T_h, Wt1T_l, HH, HH);
    transpose_split_k<<<dim3(DD/32, HH/32), tb>>>(Wt2, Wt2T_h, Wt2T_l, HH, DD);

    // txt MLP:  [NT,DD] -> [NT,HH] -> [NT,HH] -> [NT,DD]  (split outputs)
    gemm_mma<<<dim3(HH/256, NT/128), 512, GEMM_SMEM>>>(
        txtT_h, txtT_l, Wt0T_h, Wt0T_l, bt0, nullptr, ht1_h, ht1_l, NT, HH, DD, 1);
    gemm_mma<<<dim3(HH/256, NT/128), 512, GEMM_SMEM>>>(
        ht1_h, ht1_l, Wt1T_h, Wt1T_l, bt1, nullptr, ht2_h, ht2_l, NT, HH, HH, 1);
    gemm_mma<<<dim3(DD/256, NT/128), 512, GEMM_SMEM>>>(
        ht2_h, ht2_l, Wt2T_h, Wt2T_l, bt2, nullptr, ptxt_h, ptxt_l, NT, DD, HH, 0);

    // img MLP:  [BB,DD] -> [BB,HH] -> [BB,HH] -> [BB,DD]  (split outputs)
    gemm_mma<<<dim3(HH/256, BB/128), 512, GEMM_SMEM>>>(
        img_h, img_l, Wi0T_h, Wi0T_l, bi0, nullptr, hi1_h, hi1_l, BB, HH, DD, 1);
    gemm_mma<<<dim3(HH/256, BB/128), 512, GEMM_SMEM>>>(
        hi1_h, hi1_l, Wi1T_h, Wi1T_l, bi1, nullptr, hi2_h, hi2_l, BB, HH, HH, 1);
    gemm_mma<<<dim3(DD/256, BB/128), 512, GEMM_SMEM>>>(
        hi2_h, hi2_l, Wi2T_h, Wi2T_l, bi2, nullptr, pimg_h, pimg_l, BB, DD, HH, 0);

    // similarity: sim[BB, NT] = pimg @ ptxt^T  (plain output)
    gemm_mma<<<dim3(NT/256, BB/128), 512, GEMM_SMEM>>>(
        pimg_h, pimg_l, ptxt_h, ptxt_l, nullptr, sim, nullptr, nullptr, BB, NT, DD, 0);

    // per-row normalize + log-softmax pick + argmax
    row_reduce<<<BB, 256>>>(sim, tgt, temp, picked, corr);

    // final deterministic reduction
    finalize<<<1, 1024>>>(picked, corr, out, out_size);
}

// round 5
// speedup vs baseline: 2.5971x; 1.7636x over previous
#include <cuda_runtime.h>
#include <cuda_bf16.h>
#include <math.h>
#include <stdint.h>

// Problem dims (fixed by the reference)
#define BB   16384   // batch (img rows)
#define DD   512     // feature dim
#define NT   4096    // n text
#define HH   1024    // hidden

typedef __nv_bfloat16 bf16;

// ---------------- scratch (device globals; no allocs allowed) ----------------
// bf16 2-way-split operand arrays
__device__ bf16 g_img_h [ (size_t)BB * DD ], g_img_l [ (size_t)BB * DD ];
__device__ bf16 g_txtT_h[ (size_t)NT * DD ], g_txtT_l[ (size_t)NT * DD ];
__device__ bf16 g_ht1_h [ (size_t)NT * HH ], g_ht1_l [ (size_t)NT * HH ];
__device__ bf16 g_ht2_h [ (size_t)NT * HH ], g_ht2_l [ (size_t)NT * HH ];
__device__ bf16 g_ptxt_h[ (size_t)NT * DD ], g_ptxt_l[ (size_t)NT * DD ];
__device__ bf16 g_hi1_h [ (size_t)BB * HH ], g_hi1_l [ (size_t)BB * HH ];
__device__ bf16 g_hi2_h [ (size_t)BB * HH ], g_hi2_l [ (size_t)BB * HH ];
__device__ bf16 g_pimg_h[ (size_t)BB * DD ], g_pimg_l[ (size_t)BB * DD ];
__device__ bf16 g_Wi0T_h[ (size_t)HH * DD ], g_Wi0T_l[ (size_t)HH * DD ];
__device__ bf16 g_Wi1T_h[ (size_t)HH * HH ], g_Wi1T_l[ (size_t)HH * HH ];
__device__ bf16 g_Wi2T_h[ (size_t)DD * HH ], g_Wi2T_l[ (size_t)DD * HH ];
__device__ bf16 g_Wt0T_h[ (size_t)HH * DD ], g_Wt0T_l[ (size_t)HH * DD ];
__device__ bf16 g_Wt1T_h[ (size_t)HH * HH ], g_Wt1T_l[ (size_t)HH * HH ];
__device__ bf16 g_Wt2T_h[ (size_t)DD * HH ], g_Wt2T_l[ (size_t)DD * HH ];
__device__ float g_sim  [ (size_t)BB * NT ];   // [BB, NT]  (256 MB)
__device__ float g_picked [ BB ];
__device__ int   g_correct[ BB ];

__device__ __forceinline__ void split_bf(float v, bf16& h, bf16& l) {
    h = __float2bfloat16(v);
    l = __float2bfloat16(v - __bfloat162float(h));
}

// ---------------- elementwise split: in -> (hi, lo) bf16 ----------------
__global__ __launch_bounds__(256)
void split_k(const float* __restrict__ in, bf16* __restrict__ hi,
             bf16* __restrict__ lo, size_t n4) {
    size_t i = (size_t)blockIdx.x * 256 + threadIdx.x;
    size_t stride = (size_t)gridDim.x * 256;
    for (; i < n4; i += stride) {
        float4 v = reinterpret_cast<const float4*>(in)[i];
        bf16 h[4], l[4];
        split_bf(v.x, h[0], l[0]); split_bf(v.y, h[1], l[1]);
        split_bf(v.z, h[2], l[2]); split_bf(v.w, h[3], l[3]);
        reinterpret_cast<uint2*>(hi)[i] = *reinterpret_cast<uint2*>(h);
        reinterpret_cast<uint2*>(lo)[i] = *reinterpret_cast<uint2*>(l);
    }
}

// ---------------- transpose + split: in[R,C] -> hi/lo[C,R] (bf16) -----------
// Processes two tensors of identical shape (z = 0/1) to cut launch count.
__global__ void transpose_split2_k(const float* __restrict__ in0, bf16* __restrict__ h0, bf16* __restrict__ l0,
                                   const float* __restrict__ in1, bf16* __restrict__ h1, bf16* __restrict__ l1,
                                   int R, int C) {
    const float* in = (blockIdx.z == 0) ? in0 : in1;
    bf16* hi = (blockIdx.z == 0) ? h0 : h1;
    bf16* lo = (blockIdx.z == 0) ? l0 : l1;
    __shared__ float t[32][33];
    int c0 = blockIdx.x * 32, r0 = blockIdx.y * 32;
    int c = c0 + threadIdx.x;
    #pragma unroll
    for (int i = 0; i < 32; i += 8) {
        int r = r0 + threadIdx.y + i;
        t[threadIdx.y + i][threadIdx.x] = in[(size_t)r * C + c];
    }
    __syncthreads();
    int oc = r0 + threadIdx.x;
    #pragma unroll
    for (int i = 0; i < 32; i += 8) {
        int orow = c0 + threadIdx.y + i;
        float v = t[threadIdx.x][threadIdx.y + i];
        bf16 h, l; split_bf(v, h, l);
        hi[(size_t)orow * R + oc] = h;
        lo[(size_t)orow * R + oc] = l;
    }
}

// ========= mma.sync BF16 GEMM  C[M,N] = A[M,K] * B[N,K]^T  (2-way split) =====
// Block 128x256, BK=64, 16 warps (warp tile 32m x 64n), 2-stage cp.async.
// D += Ah*Bh + Ah*Bl + Al*Bh  (bf16 hi/lo, fp32 accum; error ~2^-16)

#define LDH 72                        // halves per smem row (64 + 8 pad) = 144B
#define A_TERM_B (128 * LDH * 2)      // 18432 B per A term
#define B_TERM_B (256 * LDH * 2)      // 36864 B per B term
#define STAGE_B  (2 * A_TERM_B + 2 * B_TERM_B)   // 110592 B
#define GEMM_SMEM (2 * STAGE_B)       // 221184 B

__device__ __forceinline__ uint32_t smem_u32(const void* p) {
    uint32_t a;
    asm("{ .reg .u64 t; cvta.to.shared.u64 t, %1; cvt.u32.u64 %0, t; }" : "=r"(a) : "l"(p));
    return a;
}
__device__ __forceinline__ void cp16(uint32_t dst, const void* src) {
    asm volatile("cp.async.cg.shared.global [%0], [%1], 16;" :: "r"(dst), "l"(src));
}
__device__ __forceinline__ void ldm_x4(uint32_t& r0, uint32_t& r1, uint32_t& r2,
                                       uint32_t& r3, uint32_t addr) {
    asm volatile("ldmatrix.sync.aligned.m8n8.x4.shared.b16 {%0,%1,%2,%3}, [%4];"
                 : "=r"(r0), "=r"(r1), "=r"(r2), "=r"(r3) : "r"(addr));
}
__device__ __forceinline__ void mma16(float* c, const uint32_t* a, uint32_t b0, uint32_t b1) {
    asm volatile(
        "mma.sync.aligned.m16n8k16.row.col.f32.bf16.bf16.f32 "
        "{%0,%1,%2,%3}, {%4,%5,%6,%7}, {%8,%9}, {%0,%1,%2,%3};"
        : "+f"(c[0]), "+f"(c[1]), "+f"(c[2]), "+f"(c[3])
        : "r"(a[0]), "r"(a[1]), "r"(a[2]), "r"(a[3]), "r"(b0), "r"(b1));
}

__global__ __launch_bounds__(512, 1)
void gemm_mma(const bf16* __restrict__ Ah, const bf16* __restrict__ Al,
              const bf16* __restrict__ Bh, const bf16* __restrict__ Bl,
              const float* __restrict__ bias,
              float* __restrict__ C,                       // plain output (may be null)
              bf16* __restrict__ Ch, bf16* __restrict__ Cl, // split output (may be null)
              int M, int N, int K, int relu)
{
    extern __shared__ char smraw[];
    const uint32_t smb = smem_u32(smraw);

    const int tid  = threadIdx.x;
    const int lane = tid & 31;
    const int wid  = tid >> 5;        // 0..15
    const int wm   = wid & 3;         // 4 m-groups of 32 rows
    const int wn   = wid >> 2;        // 4 n-groups of 64 cols
    const int bm   = blockIdx.y * 128;
    const int bn   = blockIdx.x * 256;

    const int KI = K >> 6;            // K/64 tiles

    // ---- cp.async stage loader: rows of 128B (8 cp16), LDH*2=144B smem rows --
    const int lr = tid >> 3;          // 0..63 row
    const int lc = tid & 7;           // 16B-chunk index (0..7)

    auto load_stage = [&](int buf, int it) {
        const int k0 = it << 6;                       // in halves
        const uint32_t st = smb + (uint32_t)buf * STAGE_B;
        const uint32_t ah_s = st;
        const uint32_t al_s = st + A_TERM_B;
        const uint32_t bh_s = st + 2 * A_TERM_B;
        const uint32_t bl_s = st + 2 * A_TERM_B + B_TERM_B;
        #pragma unroll
        for (int p = 0; p < 2; ++p) {                 // A: 128 rows
            const int row = lr + p * 64;
            const size_t g = (size_t)(bm + row) * K + k0 + lc * 8;
            const uint32_t s = (uint32_t)(row * (LDH * 2) + lc * 16);
            cp16(ah_s + s, Ah + g);
            cp16(al_s + s, Al + g);
        }
        #pragma unroll
        for (int p = 0; p < 4; ++p) {                 // B: 256 rows
            const int row = lr + p * 64;
            const size_t g = (size_t)(bn + row) * K + k0 + lc * 8;
            const uint32_t s = (uint32_t)(row * (LDH * 2) + lc * 16);
            cp16(bh_s + s, Bh + g);
            cp16(bl_s + s, Bl + g);
        }
        asm volatile("cp.async.commit_group;");
    };

    // ---- ldmatrix per-lane byte offsets ----
    const uint32_t a_off = (uint32_t)((lane & 15) * (LDH * 2) + (lane >> 4) * 16);
    const uint32_t b_off = (uint32_t)(((lane & 7) + ((lane >> 4) << 3)) * (LDH * 2)
                                      + ((lane >> 3) & 1) * 16);

    float acc[2][8][4];
    #pragma unroll
    for (int i = 0; i < 2; ++i)
        #pragma unroll
        for (int j = 0; j < 8; ++j)
            #pragma unroll
            for (int q = 0; q < 4; ++q) acc[i][j][q] = 0.0f;

    load_stage(0, 0);
    load_stage(1, 1);

    for (int it = 0; it < KI; ++it) {
        asm volatile("cp.async.wait_group 1;");
        __syncthreads();

        const int buf = it & 1;
        const uint32_t st = smb + (uint32_t)buf * STAGE_B;
        const uint32_t a_h = st + (uint32_t)(wm * 32) * (LDH * 2) + a_off;
        const uint32_t a_l = a_h + A_TERM_B;
        const uint32_t b_h = st + 2 * A_TERM_B + (uint32_t)(wn * 64) * (LDH * 2) + b_off;
        const uint32_t b_l = b_h + B_TERM_B;

        #pragma unroll
        for (int s = 0; s < 4; ++s) {                 // 4 k16-steps per BK=64
            const uint32_t koff = (uint32_t)(s << 5); // 16 halves = 32B

            uint32_t ah[2][4], al[2][4];
            #pragma unroll
            for (int mf = 0; mf < 2; ++mf) {
                const uint32_t moff = (uint32_t)(mf * 16 * (LDH * 2)) + koff;
                ldm_x4(ah[mf][0], ah[mf][1], ah[mf][2], ah[mf][3], a_h + moff);
                ldm_x4(al[mf][0], al[mf][1], al[mf][2], al[mf][3], a_l + moff);
            }
            uint32_t bh[8][2], bl[8][2];
            #pragma unroll
            for (int np = 0; np < 4; ++np) {
                const uint32_t noff = (uint32_t)(np * 16 * (LDH * 2)) + koff;
                uint32_t r0, r1, r2, r3;
                ldm_x4(r0, r1, r2, r3, b_h + noff);
                bh[np*2][0] = r0; bh[np*2][1] = r1; bh[np*2+1][0] = r2; bh[np*2+1][1] = r3;
                ldm_x4(r0, r1, r2, r3, b_l + noff);
                bl[np*2][0] = r0; bl[np*2][1] = r1; bl[np*2+1][0] = r2; bl[np*2+1][1] = r3;
            }
            #pragma unroll
            for (int mf = 0; mf < 2; ++mf)
                #pragma unroll
                for (int nf = 0; nf < 8; ++nf) {
                    float* c = acc[mf][nf];
                    mma16(c, ah[mf], bh[nf][0], bh[nf][1]);
                    mma16(c, ah[mf], bl[nf][0], bl[nf][1]);
                    mma16(c, al[mf], bh[nf][0], bh[nf][1]);
                }
        }

        __syncthreads();
        const int nt = it + 2;
        if (nt < KI) load_stage(buf, nt);
        else         asm volatile("cp.async.commit_group;");
    }

    // ---- epilogue ----
    const bool hb = (bias != nullptr);
    const bool dosplit = (Ch != nullptr);
    #pragma unroll
    for (int mf = 0; mf < 2; ++mf) {
        const int r0 = bm + wm * 32 + mf * 16 + (lane >> 2);
        #pragma unroll
        for (int nf = 0; nf < 8; ++nf) {
            const int col = bn + wn * 64 + nf * 8 + ((lane & 3) << 1);
            float v[4];
            v[0] = acc[mf][nf][0]; v[1] = acc[mf][nf][1];
            v[2] = acc[mf][nf][2]; v[3] = acc[mf][nf][3];
            if (hb) {
                const float bx = bias[col], by = bias[col + 1];
                v[0] += bx; v[1] += by; v[2] += bx; v[3] += by;
            }
            if (relu) {
                v[0] = fmaxf(v[0], 0.f); v[1] = fmaxf(v[1], 0.f);
                v[2] = fmaxf(v[2], 0.f); v[3] = fmaxf(v[3], 0.f);
            }
            const size_t o0 = (size_t)r0 * N + col;
            const size_t o1 = (size_t)(r0 + 8) * N + col;
            if (dosplit) {
                bf16 h[4], l[4];
                split_bf(v[0], h[0], l[0]); split_bf(v[1], h[1], l[1]);
                split_bf(v[2], h[2], l[2]); split_bf(v[3], h[3], l[3]);
                *reinterpret_cast<uint32_t*>(Ch + o0) = *reinterpret_cast<uint32_t*>(h);
                *reinterpret_cast<uint32_t*>(Cl + o0) = *reinterpret_cast<uint32_t*>(l);
                *reinterpret_cast<uint32_t*>(Ch + o1) = *reinterpret_cast<uint32_t*>(h + 2);
                *reinterpret_cast<uint32_t*>(Cl + o1) = *reinterpret_cast<uint32_t*>(l + 2);
            } else {
                *reinterpret_cast<float2*>(C + o0) = make_float2(v[0], v[1]);
                *reinterpret_cast<float2*>(C + o1) = make_float2(v[2], v[3]);
            }
        }
    }
}

// ---------------- per-row: normalize (x2), logsumexp, picked, argmax --------
__global__ __launch_bounds__(256)
void row_reduce(const float* __restrict__ sim, const int* __restrict__ target,
                const float* __restrict__ temp_p,
                float* __restrict__ picked, int* __restrict__ correct) {
    const int row = blockIdx.x;
    const float* s = sim + (size_t)row * NT;

    __shared__ float sv[NT];
    __shared__ float red_f[256];
    __shared__ float red_m[256];
    __shared__ int   red_i[256];

    const int tid = threadIdx.x;

    float sumsq = 0.0f;
    float vmax = -INFINITY; int vidx = 0;
    for (int j = tid; j < NT; j += 256) {
        float v = s[j];
        sv[j] = v;
        sumsq += v * v;
        if (v > vmax) { vmax = v; vidx = j; }
    }
    red_f[tid] = sumsq; red_m[tid] = vmax; red_i[tid] = vidx;
    __syncthreads();
    for (int st = 128; st > 0; st >>= 1) {
        if (tid < st) {
            red_f[tid] += red_f[tid + st];
            float om = red_m[tid + st]; int oi = red_i[tid + st];
            if (om > red_m[tid] || (om == red_m[tid] && oi < red_i[tid])) {
                red_m[tid] = om; red_i[tid] = oi;
            }
        }
        __syncthreads();
    }
    const float c1 = sqrtf(red_f[0]);
    const int   amax = red_i[0];
    const float gmax = red_m[0];
    __syncthreads();

    float ss2 = 0.0f;
    const float inv_c1 = 1.0f / c1;
    for (int j = tid; j < NT; j += 256) {
        float z = sv[j] * inv_c1;
        sv[j] = z;
        ss2 += z * z;
    }
    red_f[tid] = ss2;
    __syncthreads();
    for (int st = 128; st > 0; st >>= 1) {
        if (tid < st) red_f[tid] += red_f[tid + st];
        __syncthreads();
    }
    const float c2 = sqrtf(red_f[0]);
    __syncthreads();

    const float temp = temp_p[0];
    const float invt = 1.0f / (c2 * temp);
    const float lmax = (gmax * inv_c1) * invt;

    float se = 0.0f;
    for (int j = tid; j < NT; j += 256)
        se += expf(sv[j] * invt - lmax);
    red_f[tid] = se;
    __syncthreads();
    for (int st = 128; st > 0; st >>= 1) {
        if (tid < st) red_f[tid] += red_f[tid + st];
        __syncthreads();
    }

    if (tid == 0) {
        const float lse = lmax + logf(red_f[0]);
        const int t = target[row];
        picked[row]  = sv[t] * invt - lse;
        correct[row] = (amax == t) ? 1 : 0;
    }
}

// ---------------- deterministic final reduce --------------------------------
__global__ __launch_bounds__(1024)
void finalize(const float* __restrict__ picked, const int* __restrict__ correct,
              float* __restrict__ out, int out_size) {
    __shared__ float sp[1024];
    __shared__ int   sc[1024];
    const int tid = threadIdx.x;
    float s = 0.0f; int c = 0;
    for (int i = tid; i < BB; i += 1024) { s += picked[i]; c += correct[i]; }
    sp[tid] = s; sc[tid] = c;
    __syncthreads();
    for (int st = 512; st > 0; st >>= 1) {
        if (tid < st) { sp[tid] += sp[tid + st]; sc[tid] += sc[tid + st]; }
        __syncthreads();
    }
    if (tid == 0) {
        out[0] = -sp[0] / (float)BB;
        if (out_size >= 2) out[1] = (float)sc[0];
    }
}

// ---------------- launch ----------------------------------------------------
#define SYM(v, s) cudaGetSymbolAddress((void**)&v, s)

extern "C" void kernel_launch(void* const* d_in, const int* in_sizes, int n_in,
                              void* d_out, int out_size) {
    const float* img  = (const float*)d_in[0];
    const float* txt  = (const float*)d_in[1];
    const int*   tgt  = (const int*)  d_in[2];
    const float* temp = (const float*)d_in[3];
    const float* Wi0 = (const float*)d_in[4];  const float* bi0 = (const float*)d_in[5];
    const float* Wi1 = (const float*)d_in[6];  const float* bi1 = (const float*)d_in[7];
    const float* Wi2 = (const float*)d_in[8];  const float* bi2 = (const float*)d_in[9];
    const float* Wt0 = (const float*)d_in[10]; const float* bt0 = (const float*)d_in[11];
    const float* Wt1 = (const float*)d_in[12]; const float* bt1 = (const float*)d_in[13];
    const float* Wt2 = (const float*)d_in[14]; const float* bt2 = (const float*)d_in[15];
    // d_in[16] = logit_scale : cancels under row L2-normalization, unused.
    float* out = (float*)d_out;

    bf16 *img_h, *img_l, *txtT_h, *txtT_l, *ht1_h, *ht1_l, *ht2_h, *ht2_l;
    bf16 *ptxt_h, *ptxt_l, *hi1_h, *hi1_l, *hi2_h, *hi2_l, *pimg_h, *pimg_l;
    bf16 *Wi0T_h, *Wi0T_l, *Wi1T_h, *Wi1T_l, *Wi2T_h, *Wi2T_l;
    bf16 *Wt0T_h, *Wt0T_l, *Wt1T_h, *Wt1T_l, *Wt2T_h, *Wt2T_l;
    float *sim, *picked; int *corr;
    SYM(img_h,  g_img_h);  SYM(img_l,  g_img_l);
    SYM(txtT_h, g_txtT_h); SYM(txtT_l, g_txtT_l);
    SYM(ht1_h,  g_ht1_h);  SYM(ht1_l,  g_ht1_l);
    SYM(ht2_h,  g_ht2_h);  SYM(ht2_l,  g_ht2_l);
    SYM(ptxt_h, g_ptxt_h); SYM(ptxt_l, g_ptxt_l);
    SYM(hi1_h,  g_hi1_h);  SYM(hi1_l,  g_hi1_l);
    SYM(hi2_h,  g_hi2_h);  SYM(hi2_l,  g_hi2_l);
    SYM(pimg_h, g_pimg_h); SYM(pimg_l, g_pimg_l);
    SYM(Wi0T_h, g_Wi0T_h); SYM(Wi0T_l, g_Wi0T_l);
    SYM(Wi1T_h, g_Wi1T_h); SYM(Wi1T_l, g_Wi1T_l);
    SYM(Wi2T_h, g_Wi2T_h); SYM(Wi2T_l, g_Wi2T_l);
    SYM(Wt0T_h, g_Wt0T_h); SYM(Wt0T_l, g_Wt0T_l);
    SYM(Wt1T_h, g_Wt1T_h); SYM(Wt1T_l, g_Wt1T_l);
    SYM(Wt2T_h, g_Wt2T_h); SYM(Wt2T_l, g_Wt2T_l);
    SYM(sim, g_sim); SYM(picked, g_picked); SYM(corr, g_correct);

    cudaFuncSetAttribute(gemm_mma, cudaFuncAttributeMaxDynamicSharedMemorySize, GEMM_SMEM);

    dim3 tb(32, 8);

    // pre-kernels (5 launches so ncu -s 5 captures the first GEMM)
    transpose_split2_k<<<dim3(HH/32, DD/32, 2), tb>>>(Wi0, Wi0T_h, Wi0T_l, Wt0, Wt0T_h, Wt0T_l, DD, HH);
    transpose_split2_k<<<dim3(HH/32, HH/32, 2), tb>>>(Wi1, Wi1T_h, Wi1T_l, Wt1, Wt1T_h, Wt1T_l, HH, HH);
    transpose_split2_k<<<dim3(DD/32, HH/32, 2), tb>>>(Wi2, Wi2T_h, Wi2T_l, Wt2, Wt2T_h, Wt2T_l, HH, DD);
    transpose_split2_k<<<dim3(NT/32, DD/32, 1), tb>>>(txt, txtT_h, txtT_l, txt, txtT_h, txtT_l, DD, NT);
    split_k<<<256, 256>>>(img, img_h, img_l, (size_t)BB * DD / 4);

    // img MLP:  [BB,DD] -> [BB,HH] -> [BB,HH] -> [BB,DD]  (split outputs)
    gemm_mma<<<dim3(HH/256, BB/128), 512, GEMM_SMEM>>>(
        img_h, img_l, Wi0T_h, Wi0T_l, bi0, nullptr, hi1_h, hi1_l, BB, HH, DD, 1);
    gemm_mma<<<dim3(HH/256, BB/128), 512, GEMM_SMEM>>>(
        hi1_h, hi1_l, Wi1T_h, Wi1T_l, bi1, nullptr, hi2_h, hi2_l, BB, HH, HH, 1);
    gemm_mma<<<dim3(DD/256, BB/128), 512, GEMM_SMEM>>>(
        hi2_h, hi2_l, Wi2T_h, Wi2T_l, bi2, nullptr, pimg_h, pimg_l, BB, DD, HH, 0);

    // txt MLP:  [NT,DD] -> [NT,HH] -> [NT,HH] -> [NT,DD]  (split outputs)
    gemm_mma<<<dim3(HH/256, NT/128), 512, GEMM_SMEM>>>(
        txtT_h, txtT_l, Wt0T_h, Wt0T_l, bt0, nullptr, ht1_h, ht1_l, NT, HH, DD, 1);
    gemm_mma<<<dim3(HH/256, NT/128), 512, GEMM_SMEM>>>(
        ht1_h, ht1_l, Wt1T_h, Wt1T_l, bt1, nullptr, ht2_h, ht2_l, NT, HH, HH, 1);
    gemm_mma<<<dim3(DD/256, NT/128), 512, GEMM_SMEM>>>(
        ht2_h, ht2_l, Wt2T_h, Wt2T_l, bt2, nullptr, ptxt_h, ptxt_l, NT, DD, HH, 0);

    // similarity: sim[BB, NT] = pimg @ ptxt^T  (plain fp32 output)
    gemm_mma<<<dim3(NT/256, BB/128), 512, GEMM_SMEM>>>(
        pimg_h, pimg_l, ptxt_h, ptxt_l, nullptr, sim, nullptr, nullptr, BB, NT, DD, 0);

    // per-row normalize + log-softmax pick + argmax
    row_reduce<<<BB, 256>>>(sim, tgt, temp, picked, corr);

    // final deterministic reduction
    finalize<<<1, 1024>>>(picked, corr, out, out_size);
}

// round 6
// speedup vs baseline: 2.6110x; 1.0054x over previous
#include <cuda_runtime.h>
#include <cuda_bf16.h>
#include <math.h>
#include <stdint.h>

// Problem dims (fixed by the reference)
#define BB   16384   // batch (img rows)
#define DD   512     // feature dim
#define NT   4096    // n text
#define HH   1024    // hidden

typedef __nv_bfloat16 bf16;

// ---------------- scratch (device globals; no allocs allowed) ----------------
__device__ bf16 g_img_h [ (size_t)BB * DD ], g_img_l [ (size_t)BB * DD ];
__device__ bf16 g_txtT_h[ (size_t)NT * DD ], g_txtT_l[ (size_t)NT * DD ];
__device__ bf16 g_ht1_h [ (size_t)NT * HH ], g_ht1_l [ (size_t)NT * HH ];
__device__ bf16 g_ht2_h [ (size_t)NT * HH ], g_ht2_l [ (size_t)NT * HH ];
__device__ bf16 g_ptxt_h[ (size_t)NT * DD ], g_ptxt_l[ (size_t)NT * DD ];
__device__ bf16 g_hi1_h [ (size_t)BB * HH ], g_hi1_l [ (size_t)BB * HH ];
__device__ bf16 g_hi2_h [ (size_t)BB * HH ], g_hi2_l [ (size_t)BB * HH ];
__device__ bf16 g_pimg_h[ (size_t)BB * DD ], g_pimg_l[ (size_t)BB * DD ];
__device__ bf16 g_Wi0T_h[ (size_t)HH * DD ], g_Wi0T_l[ (size_t)HH * DD ];
__device__ bf16 g_Wi1T_h[ (size_t)HH * HH ], g_Wi1T_l[ (size_t)HH * HH ];
__device__ bf16 g_Wi2T_h[ (size_t)DD * HH ], g_Wi2T_l[ (size_t)DD * HH ];
__device__ bf16 g_Wt0T_h[ (size_t)HH * DD ], g_Wt0T_l[ (size_t)HH * DD ];
__device__ bf16 g_Wt1T_h[ (size_t)HH * HH ], g_Wt1T_l[ (size_t)HH * HH ];
__device__ bf16 g_Wt2T_h[ (size_t)DD * HH ], g_Wt2T_l[ (size_t)DD * HH ];
__device__ float g_sim  [ (size_t)BB * NT ];   // [BB, NT]  (256 MB)
__device__ float g_picked [ BB ];
__device__ int   g_correct[ BB ];

__device__ __forceinline__ void split_bf(float v, bf16& h, bf16& l) {
    h = __float2bfloat16(v);
    l = __float2bfloat16(v - __bfloat162float(h));
}

// ---------------- elementwise split: in -> (hi, lo) bf16 ----------------
__global__ __launch_bounds__(256)
void split_k(const float* __restrict__ in, bf16* __restrict__ hi,
             bf16* __restrict__ lo, size_t n4) {
    size_t i = (size_t)blockIdx.x * 256 + threadIdx.x;
    size_t stride = (size_t)gridDim.x * 256;
    for (; i < n4; i += stride) {
        float4 v = reinterpret_cast<const float4*>(in)[i];
        bf16 h[4], l[4];
        split_bf(v.x, h[0], l[0]); split_bf(v.y, h[1], l[1]);
        split_bf(v.z, h[2], l[2]); split_bf(v.w, h[3], l[3]);
        reinterpret_cast<uint2*>(hi)[i] = *reinterpret_cast<uint2*>(h);
        reinterpret_cast<uint2*>(lo)[i] = *reinterpret_cast<uint2*>(l);
    }
}

// ---------------- transpose + split: in[R,C] -> hi/lo[C,R] (bf16) -----------
__global__ void transpose_split2_k(const float* __restrict__ in0, bf16* __restrict__ h0, bf16* __restrict__ l0,
                                   const float* __restrict__ in1, bf16* __restrict__ h1, bf16* __restrict__ l1,
                                   int R, int C) {
    const float* in = (blockIdx.z == 0) ? in0 : in1;
    bf16* hi = (blockIdx.z == 0) ? h0 : h1;
    bf16* lo = (blockIdx.z == 0) ? l0 : l1;
    __shared__ float t[32][33];
    int c0 = blockIdx.x * 32, r0 = blockIdx.y * 32;
    int c = c0 + threadIdx.x;
    #pragma unroll
    for (int i = 0; i < 32; i += 8) {
        int r = r0 + threadIdx.y + i;
        t[threadIdx.y + i][threadIdx.x] = in[(size_t)r * C + c];
    }
    __syncthreads();
    int oc = r0 + threadIdx.x;
    #pragma unroll
    for (int i = 0; i < 32; i += 8) {
        int orow = c0 + threadIdx.y + i;
        float v = t[threadIdx.x][threadIdx.y + i];
        bf16 h, l; split_bf(v, h, l);
        hi[(size_t)orow * R + oc] = h;
        lo[(size_t)orow * R + oc] = l;
    }
}

// ========= mma.sync BF16 GEMM  C[M,N] = A[M,K] * B[N,K]^T  (2-way split) =====
// Block 128x256, BK=64, 16 warps (warp tile 32m x 64n), 2-stage cp.async.
// D += Ah*Bh + Ah*Bl + Al*Bh, issued TERM-MAJOR to break accumulator RAW chains.

#define LDH 72                        // halves per smem row (64 + 8 pad) = 144B
#define A_TERM_B (128 * LDH * 2)
#define B_TERM_B (256 * LDH * 2)
#define STAGE_B  (2 * A_TERM_B + 2 * B_TERM_B)   // 110592 B
#define GEMM_SMEM (2 * STAGE_B)       // 221184 B

__device__ __forceinline__ uint32_t smem_u32(const void* p) {
    uint32_t a;
    asm("{ .reg .u64 t; cvta.to.shared.u64 t, %1; cvt.u32.u64 %0, t; }" : "=r"(a) : "l"(p));
    return a;
}
__device__ __forceinline__ void cp16(uint32_t dst, const void* src) {
    asm volatile("cp.async.cg.shared.global [%0], [%1], 16;" :: "r"(dst), "l"(src));
}
__device__ __forceinline__ void ldm_x4(uint32_t& r0, uint32_t& r1, uint32_t& r2,
                                       uint32_t& r3, uint32_t addr) {
    asm volatile("ldmatrix.sync.aligned.m8n8.x4.shared.b16 {%0,%1,%2,%3}, [%4];"
                 : "=r"(r0), "=r"(r1), "=r"(r2), "=r"(r3) : "r"(addr));
}
__device__ __forceinline__ void mma16(float* c, const uint32_t* a, uint32_t b0, uint32_t b1) {
    asm volatile(
        "mma.sync.aligned.m16n8k16.row.col.f32.bf16.bf16.f32 "
        "{%0,%1,%2,%3}, {%4,%5,%6,%7}, {%8,%9}, {%0,%1,%2,%3};"
        : "+f"(c[0]), "+f"(c[1]), "+f"(c[2]), "+f"(c[3])
        : "r"(a[0]), "r"(a[1]), "r"(a[2]), "r"(a[3]), "r"(b0), "r"(b1));
}

__global__ __launch_bounds__(512, 1)
void gemm_mma(const bf16* __restrict__ Ah, const bf16* __restrict__ Al,
              const bf16* __restrict__ Bh, const bf16* __restrict__ Bl,
              const float* __restrict__ bias,
              float* __restrict__ C,                       // plain output (may be null)
              bf16* __restrict__ Ch, bf16* __restrict__ Cl, // split output (may be null)
              int M, int N, int K, int relu)
{
    extern __shared__ char smraw[];
    const uint32_t smb = smem_u32(smraw);

    const int tid  = threadIdx.x;
    const int lane = tid & 31;
    const int wid  = tid >> 5;        // 0..15
    const int wm   = wid & 3;         // 4 m-groups of 32 rows
    const int wn   = wid >> 2;        // 4 n-groups of 64 cols
    const int bm   = blockIdx.y * 128;
    const int bn   = blockIdx.x * 256;

    const int KI = K >> 6;            // K/64 tiles

    const int lr = tid >> 3;          // 0..63 row
    const int lc = tid & 7;           // 16B-chunk index (0..7)

    auto load_stage = [&](int buf, int it) {
        const int k0 = it << 6;
        const uint32_t st = smb + (uint32_t)buf * STAGE_B;
        const uint32_t ah_s = st;
        const uint32_t al_s = st + A_TERM_B;
        const uint32_t bh_s = st + 2 * A_TERM_B;
        const uint32_t bl_s = st + 2 * A_TERM_B + B_TERM_B;
        #pragma unroll
        for (int p = 0; p < 2; ++p) {                 // A: 128 rows
            const int row = lr + p * 64;
            const size_t g = (size_t)(bm + row) * K + k0 + lc * 8;
            const uint32_t s = (uint32_t)(row * (LDH * 2) + lc * 16);
            cp16(ah_s + s, Ah + g);
            cp16(al_s + s, Al + g);
        }
        #pragma unroll
        for (int p = 0; p < 4; ++p) {                 // B: 256 rows
            const int row = lr + p * 64;
            const size_t g = (size_t)(bn + row) * K + k0 + lc * 8;
            const uint32_t s = (uint32_t)(row * (LDH * 2) + lc * 16);
            cp16(bh_s + s, Bh + g);
            cp16(bl_s + s, Bl + g);
        }
        asm volatile("cp.async.commit_group;");
    };

    const uint32_t a_off = (uint32_t)((lane & 15) * (LDH * 2) + (lane >> 4) * 16);
    const uint32_t b_off = (uint32_t)(((lane & 7) + ((lane >> 4) << 3)) * (LDH * 2)
                                      + ((lane >> 3) & 1) * 16);

    float acc[2][8][4];
    #pragma unroll
    for (int i = 0; i < 2; ++i)
        #pragma unroll
        for (int j = 0; j < 8; ++j)
            #pragma unroll
            for (int q = 0; q < 4; ++q) acc[i][j][q] = 0.0f;

    load_stage(0, 0);
    load_stage(1, 1);

    for (int it = 0; it < KI; ++it) {
        asm volatile("cp.async.wait_group 1;");
        __syncthreads();

        const int buf = it & 1;
        const uint32_t st = smb + (uint32_t)buf * STAGE_B;
        const uint32_t a_h = st + (uint32_t)(wm * 32) * (LDH * 2) + a_off;
        const uint32_t a_l = a_h + A_TERM_B;
        const uint32_t b_h = st + 2 * A_TERM_B + (uint32_t)(wn * 64) * (LDH * 2) + b_off;
        const uint32_t b_l = b_h + B_TERM_B;

        #pragma unroll
        for (int s = 0; s < 4; ++s) {                 // 4 k16-steps per BK=64
            const uint32_t koff = (uint32_t)(s << 5); // 16 halves = 32B

            uint32_t ah[2][4], al[2][4];
            #pragma unroll
            for (int mf = 0; mf < 2; ++mf) {
                const uint32_t moff = (uint32_t)(mf * 16 * (LDH * 2)) + koff;
                ldm_x4(ah[mf][0], ah[mf][1], ah[mf][2], ah[mf][3], a_h + moff);
                ldm_x4(al[mf][0], al[mf][1], al[mf][2], al[mf][3], a_l + moff);
            }
            uint32_t bh[8][2], bl[8][2];
            #pragma unroll
            for (int np = 0; np < 4; ++np) {
                const uint32_t noff = (uint32_t)(np * 16 * (LDH * 2)) + koff;
                uint32_t r0, r1, r2, r3;
                ldm_x4(r0, r1, r2, r3, b_h + noff);
                bh[np*2][0] = r0; bh[np*2][1] = r1; bh[np*2+1][0] = r2; bh[np*2+1][1] = r3;
                ldm_x4(r0, r1, r2, r3, b_l + noff);
                bl[np*2][0] = r0; bl[np*2][1] = r1; bl[np*2+1][0] = r2; bl[np*2+1][1] = r3;
            }
            // TERM-MAJOR issue: 16 independent MMAs between touches of the
            // same accumulator -> HMMA RAW latency fully hidden.
            #pragma unroll
            for (int mf = 0; mf < 2; ++mf)
                #pragma unroll
                for (int nf = 0; nf < 8; ++nf)
                    mma16(acc[mf][nf], ah[mf], bh[nf][0], bh[nf][1]);
            #pragma unroll
            for (int mf = 0; mf < 2; ++mf)
                #pragma unroll
                for (int nf = 0; nf < 8; ++nf)
                    mma16(acc[mf][nf], ah[mf], bl[nf][0], bl[nf][1]);
            #pragma unroll
            for (int mf = 0; mf < 2; ++mf)
                #pragma unroll
                for (int nf = 0; nf < 8; ++nf)
                    mma16(acc[mf][nf], al[mf], bh[nf][0], bh[nf][1]);
        }

        __syncthreads();
        const int nt = it + 2;
        if (nt < KI) load_stage(buf, nt);
        else         asm volatile("cp.async.commit_group;");
    }

    // ---- epilogue ----
    const bool hb = (bias != nullptr);
    const bool dosplit = (Ch != nullptr);
    #pragma unroll
    for (int mf = 0; mf < 2; ++mf) {
        const int r0 = bm + wm * 32 + mf * 16 + (lane >> 2);
        #pragma unroll
        for (int nf = 0; nf < 8; ++nf) {
            const int col = bn + wn * 64 + nf * 8 + ((lane & 3) << 1);
            float v[4];
            v[0] = acc[mf][nf][0]; v[1] = acc[mf][nf][1];
            v[2] = acc[mf][nf][2]; v[3] = acc[mf][nf][3];
            if (hb) {
                const float bx = bias[col], by = bias[col + 1];
                v[0] += bx; v[1] += by; v[2] += bx; v[3] += by;
            }
            if (relu) {
                v[0] = fmaxf(v[0], 0.f); v[1] = fmaxf(v[1], 0.f);
                v[2] = fmaxf(v[2], 0.f); v[3] = fmaxf(v[3], 0.f);
            }
            const size_t o0 = (size_t)r0 * N + col;
            const size_t o1 = (size_t)(r0 + 8) * N + col;
            if (dosplit) {
                bf16 h[4], l[4];
                split_bf(v[0], h[0], l[0]); split_bf(v[1], h[1], l[1]);
                split_bf(v[2], h[2], l[2]); split_bf(v[3], h[3], l[3]);
                *reinterpret_cast<uint32_t*>(Ch + o0) = *reinterpret_cast<uint32_t*>(h);
                *reinterpret_cast<uint32_t*>(Cl + o0) = *reinterpret_cast<uint32_t*>(l);
                *reinterpret_cast<uint32_t*>(Ch + o1) = *reinterpret_cast<uint32_t*>(h + 2);
                *reinterpret_cast<uint32_t*>(Cl + o1) = *reinterpret_cast<uint32_t*>(l + 2);
            } else {
                *reinterpret_cast<float2*>(C + o0) = make_float2(v[0], v[1]);
                *reinterpret_cast<float2*>(C + o1) = make_float2(v[2], v[3]);
            }
        }
    }
}

// ---------------- per-row: normalize (x2), logsumexp, picked, argmax --------
__global__ __launch_bounds__(256)
void row_reduce(const float* __restrict__ sim, const int* __restrict__ target,
                const float* __restrict__ temp_p,
                float* __restrict__ picked, int* __restrict__ correct) {
    const int row = blockIdx.x;
    const float* s = sim + (size_t)row * NT;

    __shared__ float sv[NT];
    __shared__ float red_f[256];
    __shared__ float red_m[256];
    __shared__ int   red_i[256];

    const int tid = threadIdx.x;

    float sumsq = 0.0f;
    float vmax = -INFINITY; int vidx = 0;
    for (int j = tid; j < NT; j += 256) {
        float v = s[j];
        sv[j] = v;
        sumsq += v * v;
        if (v > vmax) { vmax = v; vidx = j; }
    }
    red_f[tid] = sumsq; red_m[tid] = vmax; red_i[tid] = vidx;
    __syncthreads();
    for (int st = 128; st > 0; st >>= 1) {
        if (tid < st) {
            red_f[tid] += red_f[tid + st];
            float om = red_m[tid + st]; int oi = red_i[tid + st];
            if (om > red_m[tid] || (om == red_m[tid] && oi < red_i[tid])) {
                red_m[tid] = om; red_i[tid] = oi;
            }
        }
        __syncthreads();
    }
    const float c1 = sqrtf(red_f[0]);
    const int   amax = red_i[0];
    const float gmax = red_m[0];
    __syncthreads();

    float ss2 = 0.0f;
    const float inv_c1 = 1.0f / c1;
    for (int j = tid; j < NT; j += 256) {
        float z = sv[j] * inv_c1;
        sv[j] = z;
        ss2 += z * z;
    }
    red_f[tid] = ss2;
    __syncthreads();
    for (int st = 128; st > 0; st >>= 1) {
        if (tid < st) red_f[tid] += red_f[tid + st];
        __syncthreads();
    }
    const float c2 = sqrtf(red_f[0]);
    __syncthreads();

    const float temp = temp_p[0];
    const float invt = 1.0f / (c2 * temp);
    const float lmax = (gmax * inv_c1) * invt;

    float se = 0.0f;
    for (int j = tid; j < NT; j += 256)
        se += expf(sv[j] * invt - lmax);
    red_f[tid] = se;
    __syncthreads();
    for (int st = 128; st > 0; st >>= 1) {
        if (tid < st) red_f[tid] += red_f[tid + st];
        __syncthreads();
    }

    if (tid == 0) {
        const float lse = lmax + logf(red_f[0]);
        const int t = target[row];
        picked[row]  = sv[t] * invt - lse;
        correct[row] = (amax == t) ? 1 : 0;
    }
}

// ---------------- deterministic final reduce --------------------------------
__global__ __launch_bounds__(1024)
void finalize(const float* __restrict__ picked, const int* __restrict__ correct,
              float* __restrict__ out, int out_size) {
    __shared__ float sp[1024];
    __shared__ int   sc[1024];
    const int tid = threadIdx.x;
    float s = 0.0f; int c = 0;
    for (int i = tid; i < BB; i += 1024) { s += picked[i]; c += correct[i]; }
    sp[tid] = s; sc[tid] = c;
    __syncthreads();
    for (int st = 512; st > 0; st >>= 1) {
        if (tid < st) { sp[tid] += sp[tid + st]; sc[tid] += sc[tid + st]; }
        __syncthreads();
    }
    if (tid == 0) {
        out[0] = -sp[0] / (float)BB;
        if (out_size >= 2) out[1] = (float)sc[0];
    }
}

// ---------------- launch ----------------------------------------------------
#define SYM(v, s) cudaGetSymbolAddress((void**)&v, s)

extern "C" void kernel_launch(void* const* d_in, const int* in_sizes, int n_in,
                              void* d_out, int out_size) {
    const float* img  = (const float*)d_in[0];
    const float* txt  = (const float*)d_in[1];
    const int*   tgt  = (const int*)  d_in[2];
    const float* temp = (const float*)d_in[3];
    const float* Wi0 = (const float*)d_in[4];  const float* bi0 = (const float*)d_in[5];
    const float* Wi1 = (const float*)d_in[6];  const float* bi1 = (const float*)d_in[7];
    const float* Wi2 = (const float*)d_in[8];  const float* bi2 = (const float*)d_in[9];
    const float* Wt0 = (const float*)d_in[10]; const float* bt0 = (const float*)d_in[11];
    const float* Wt1 = (const float*)d_in[12]; const float* bt1 = (const float*)d_in[13];
    const float* Wt2 = (const float*)d_in[14]; const float* bt2 = (const float*)d_in[15];
    // d_in[16] = logit_scale : cancels under row L2-normalization, unused.
    float* out = (float*)d_out;

    bf16 *img_h, *img_l, *txtT_h, *txtT_l, *ht1_h, *ht1_l, *ht2_h, *ht2_l;
    bf16 *ptxt_h, *ptxt_l, *hi1_h, *hi1_l, *hi2_h, *hi2_l, *pimg_h, *pimg_l;
    bf16 *Wi0T_h, *Wi0T_l, *Wi1T_h, *Wi1T_l, *Wi2T_h, *Wi2T_l;
    bf16 *Wt0T_h, *Wt0T_l, *Wt1T_h, *Wt1T_l, *Wt2T_h, *Wt2T_l;
    float *sim, *picked; int *corr;
    SYM(img_h,  g_img_h);  SYM(img_l,  g_img_l);
    SYM(txtT_h, g_txtT_h); SYM(txtT_l, g_txtT_l);
    SYM(ht1_h,  g_ht1_h);  SYM(ht1_l,  g_ht1_l);
    SYM(ht2_h,  g_ht2_h);  SYM(ht2_l,  g_ht2_l);
    SYM(ptxt_h, g_ptxt_h); SYM(ptxt_l, g_ptxt_l);
    SYM(hi1_h,  g_hi1_h);  SYM(hi1_l,  g_hi1_l);
    SYM(hi2_h,  g_hi2_h);  SYM(hi2_l,  g_hi2_l);
    SYM(pimg_h, g_pimg_h); SYM(pimg_l, g_pimg_l);
    SYM(Wi0T_h, g_Wi0T_h); SYM(Wi0T_l, g_Wi0T_l);
    SYM(Wi1T_h, g_Wi1T_h); SYM(Wi1T_l, g_Wi1T_l);
    SYM(Wi2T_h, g_Wi2T_h); SYM(Wi2T_l, g_Wi2T_l);
    SYM(Wt0T_h, g_Wt0T_h); SYM(Wt0T_l, g_Wt0T_l);
    SYM(Wt1T_h, g_Wt1T_h); SYM(Wt1T_l, g_Wt1T_l);
    SYM(Wt2T_h, g_Wt2T_h); SYM(Wt2T_l, g_Wt2T_l);
    SYM(sim, g_sim); SYM(picked, g_picked); SYM(corr, g_correct);

    cudaFuncSetAttribute(gemm_mma, cudaFuncAttributeMaxDynamicSharedMemorySize, GEMM_SMEM);

    dim3 tb(32, 8);

    // pre-kernels
    transpose_split2_k<<<dim3(HH/32, DD/32, 2), tb>>>(Wi0, Wi0T_h, Wi0T_l, Wt0, Wt0T_h, Wt0T_l, DD, HH);
    transpose_split2_k<<<dim3(HH/32, HH/32, 2), tb>>>(Wi1, Wi1T_h, Wi1T_l, Wt1, Wt1T_h, Wt1T_l, HH, HH);
    transpose_split2_k<<<dim3(DD/32, HH/32, 2), tb>>>(Wi2, Wi2T_h, Wi2T_l, Wt2, Wt2T_h, Wt2T_l, HH, DD);
    transpose_split2_k<<<dim3(NT/32, DD/32, 1), tb>>>(txt, txtT_h, txtT_l, txt, txtT_h, txtT_l, DD, NT);
    split_k<<<256, 256>>>(img, img_h, img_l, (size_t)BB * DD / 4);

    // img MLP:  [BB,DD] -> [BB,HH] -> [BB,HH] -> [BB,DD]  (split outputs)
    gemm_mma<<<dim3(HH/256, BB/128), 512, GEMM_SMEM>>>(
        img_h, img_l, Wi0T_h, Wi0T_l, bi0, nullptr, hi1_h, hi1_l, BB, HH, DD, 1);
    gemm_mma<<<dim3(HH/256, BB/128), 512, GEMM_SMEM>>>(
        hi1_h, hi1_l, Wi1T_h, Wi1T_l, bi1, nullptr, hi2_h, hi2_l, BB, HH, HH, 1);
    gemm_mma<<<dim3(DD/256, BB/128), 512, GEMM_SMEM>>>(
        hi2_h, hi2_l, Wi2T_h, Wi2T_l, bi2, nullptr, pimg_h, pimg_l, BB, DD, HH, 0);

    // txt MLP:  [NT,DD] -> [NT,HH] -> [NT,HH] -> [NT,DD]  (split outputs)
    gemm_mma<<<dim3(HH/256, NT/128), 512, GEMM_SMEM>>>(
        txtT_h, txtT_l, Wt0T_h, Wt0T_l, bt0, nullptr, ht1_h, ht1_l, NT, HH, DD, 1);
    gemm_mma<<<dim3(HH/256, NT/128), 512, GEMM_SMEM>>>(
        ht1_h, ht1_l, Wt1T_h, Wt1T_l, bt1, nullptr, ht2_h, ht2_l, NT, HH, HH, 1);
    gemm_mma<<<dim3(DD/256, NT/128), 512, GEMM_SMEM>>>(
        ht2_h, ht2_l, Wt2T_h, Wt2T_l, bt2, nullptr, ptxt_h, ptxt_l, NT, DD, HH, 0);

    // similarity: sim[BB, NT] = pimg @ ptxt^T  (plain fp32 output)
    gemm_mma<<<dim3(NT/256, BB/128), 512, GEMM_SMEM>>>(
        pimg_h, pimg_l, ptxt_h, ptxt_l, nullptr, sim, nullptr, nullptr, BB, NT, DD, 0);

    // per-row normalize + log-softmax pick + argmax
    row_reduce<<<BB, 256>>>(sim, tgt, temp, picked, corr);

    // final deterministic reduction
    finalize<<<1, 1024>>>(picked, corr, out, out_size);
}

// round 7
// speedup vs baseline: 3.4431x; 1.3187x over previous
#include <cuda_runtime.h>
#include <cuda_fp16.h>
#include <math.h>
#include <stdint.h>

// Problem dims (fixed by the reference)
#define BB   16384   // batch (img rows)
#define DD   512     // feature dim
#define NT   4096    // n text
#define HH   1024    // hidden

typedef __half hf;

// ---------------- scratch (device globals; no allocs allowed) ----------------
// A-side operands: 2-part fp16 (h + l). B-side operands: single fp16.
__device__ hf g_img_h [ (size_t)BB * DD ], g_img_l [ (size_t)BB * DD ];
__device__ hf g_txtT_h[ (size_t)NT * DD ], g_txtT_l[ (size_t)NT * DD ];
__device__ hf g_ht1_h [ (size_t)NT * HH ], g_ht1_l [ (size_t)NT * HH ];
__device__ hf g_ht2_h [ (size_t)NT * HH ], g_ht2_l [ (size_t)NT * HH ];
__device__ hf g_ptxt_h[ (size_t)NT * DD ];                      // B of sim: single
__device__ hf g_hi1_h [ (size_t)BB * HH ], g_hi1_l [ (size_t)BB * HH ];
__device__ hf g_hi2_h [ (size_t)BB * HH ], g_hi2_l [ (size_t)BB * HH ];
__device__ hf g_pimg_h[ (size_t)BB * DD ], g_pimg_l[ (size_t)BB * DD ];
__device__ hf g_Wi0T  [ (size_t)HH * DD ];
__device__ hf g_Wi1T  [ (size_t)HH * HH ];
__device__ hf g_Wi2T  [ (size_t)DD * HH ];
__device__ hf g_Wt0T  [ (size_t)HH * DD ];
__device__ hf g_Wt1T  [ (size_t)HH * HH ];
__device__ hf g_Wt2T  [ (size_t)DD * HH ];
__device__ float g_sim  [ (size_t)BB * NT ];   // [BB, NT]  (256 MB)
__device__ float g_picked [ BB ];
__device__ int   g_correct[ BB ];

__device__ __forceinline__ void split_hf(float v, hf& h, hf& l) {
    h = __float2half_rn(v);
    l = __float2half_rn(v - __half2float(h));
}

// ---------------- elementwise split: in -> (hi, lo) fp16 ----------------
__global__ __launch_bounds__(256)
void split_k(const float* __restrict__ in, hf* __restrict__ hi,
             hf* __restrict__ lo, size_t n4) {
    size_t i = (size_t)blockIdx.x * 256 + threadIdx.x;
    size_t stride = (size_t)gridDim.x * 256;
    for (; i < n4; i += stride) {
        float4 v = reinterpret_cast<const float4*>(in)[i];
        hf h[4], l[4];
        split_hf(v.x, h[0], l[0]); split_hf(v.y, h[1], l[1]);
        split_hf(v.z, h[2], l[2]); split_hf(v.w, h[3], l[3]);
        reinterpret_cast<uint2*>(hi)[i] = *reinterpret_cast<uint2*>(h);
        reinterpret_cast<uint2*>(lo)[i] = *reinterpret_cast<uint2*>(l);
    }
}

// ---------------- transpose (+ optional split): in[R,C] -> [C,R] fp16 -------
// Two tensors per launch via blockIdx.z; lo pointer may be null (single mode).
__global__ void transpose_split2_k(const float* __restrict__ in0, hf* __restrict__ h0, hf* __restrict__ l0,
                                   const float* __restrict__ in1, hf* __restrict__ h1, hf* __restrict__ l1,
                                   int R, int C) {
    const float* in = (blockIdx.z == 0) ? in0 : in1;
    hf* hi = (blockIdx.z == 0) ? h0 : h1;
    hf* lo = (blockIdx.z == 0) ? l0 : l1;
    __shared__ float t[32][33];
    int c0 = blockIdx.x * 32, r0 = blockIdx.y * 32;
    int c = c0 + threadIdx.x;
    #pragma unroll
    for (int i = 0; i < 32; i += 8) {
        int r = r0 + threadIdx.y + i;
        t[threadIdx.y + i][threadIdx.x] = in[(size_t)r * C + c];
    }
    __syncthreads();
    int oc = r0 + threadIdx.x;
    #pragma unroll
    for (int i = 0; i < 32; i += 8) {
        int orow = c0 + threadIdx.y + i;
        float v = t[threadIdx.x][threadIdx.y + i];
        if (lo) {
            hf h, l; split_hf(v, h, l);
            hi[(size_t)orow * R + oc] = h;
            lo[(size_t)orow * R + oc] = l;
        } else {
            hi[(size_t)orow * R + oc] = __float2half_rn(v);
        }
    }
}

// ====== mma.sync FP16 GEMM  C[M,N] = A[M,K] * B[N,K]^T  (A 2-part, B 1-part) =
// Block 128x256, BK=64, 16 warps (warp tile 32m x 64n), 3-stage cp.async.
// D += Ah*Bh + Al*Bh  (fp32 accum; residual = A*(B-Bh) ~ 2^-12 rel)

#define LDH 72                        // halves per smem row (64 + 8 pad) = 144B
#define A_TERM_B (128 * LDH * 2)      // 18432 B per A term
#define B_TERM_B (256 * LDH * 2)      // 36864 B
#define STAGE_B  (2 * A_TERM_B + B_TERM_B)   // 73728 B
#define NSTAGE   3
#define GEMM_SMEM (NSTAGE * STAGE_B)  // 221184 B

__device__ __forceinline__ uint32_t smem_u32(const void* p) {
    uint32_t a;
    asm("{ .reg .u64 t; cvta.to.shared.u64 t, %1; cvt.u32.u64 %0, t; }" : "=r"(a) : "l"(p));
    return a;
}
__device__ __forceinline__ void cp16(uint32_t dst, const void* src) {
    asm volatile("cp.async.cg.shared.global [%0], [%1], 16;" :: "r"(dst), "l"(src));
}
__device__ __forceinline__ void ldm_x4(uint32_t& r0, uint32_t& r1, uint32_t& r2,
                                       uint32_t& r3, uint32_t addr) {
    asm volatile("ldmatrix.sync.aligned.m8n8.x4.shared.b16 {%0,%1,%2,%3}, [%4];"
                 : "=r"(r0), "=r"(r1), "=r"(r2), "=r"(r3) : "r"(addr));
}
__device__ __forceinline__ void mma16(float* c, const uint32_t* a, uint32_t b0, uint32_t b1) {
    asm volatile(
        "mma.sync.aligned.m16n8k16.row.col.f32.f16.f16.f32 "
        "{%0,%1,%2,%3}, {%4,%5,%6,%7}, {%8,%9}, {%0,%1,%2,%3};"
        : "+f"(c[0]), "+f"(c[1]), "+f"(c[2]), "+f"(c[3])
        : "r"(a[0]), "r"(a[1]), "r"(a[2]), "r"(a[3]), "r"(b0), "r"(b1));
}

__global__ __launch_bounds__(512, 1)
void gemm_mma(const hf* __restrict__ Ah, const hf* __restrict__ Al,
              const hf* __restrict__ Bh,
              const float* __restrict__ bias,
              float* __restrict__ C,                     // fp32 output (may be null)
              hf* __restrict__ Ch, hf* __restrict__ Cl,  // fp16 output(s) (may be null)
              int M, int N, int K, int relu)
{
    extern __shared__ char smraw[];
    const uint32_t smb = smem_u32(smraw);

    const int tid  = threadIdx.x;
    const int lane = tid & 31;
    const int wid  = tid >> 5;        // 0..15
    const int wm   = wid & 3;         // 4 m-groups of 32 rows
    const int wn   = wid >> 2;        // 4 n-groups of 64 cols
    const int bm   = blockIdx.y * 128;
    const int bn   = blockIdx.x * 256;

    const int KI = K >> 6;            // K/64 tiles

    const int lr = tid >> 3;          // 0..63 row
    const int lc = tid & 7;           // 16B-chunk index (0..7)

    auto load_stage = [&](int buf, int it) {
        const int k0 = it << 6;
        const uint32_t st = smb + (uint32_t)buf * STAGE_B;
        const uint32_t ah_s = st;
        const uint32_t al_s = st + A_TERM_B;
        const uint32_t bh_s = st + 2 * A_TERM_B;
        #pragma unroll
        for (int p = 0; p < 2; ++p) {                 // A: 128 rows (h + l)
            const int row = lr + p * 64;
            const size_t g = (size_t)(bm + row) * K + k0 + lc * 8;
            const uint32_t s = (uint32_t)(row * (LDH * 2) + lc * 16);
            cp16(ah_s + s, Ah + g);
            cp16(al_s + s, Al + g);
        }
        #pragma unroll
        for (int p = 0; p < 4; ++p) {                 // B: 256 rows (h only)
            const int row = lr + p * 64;
            const size_t g = (size_t)(bn + row) * K + k0 + lc * 8;
            const uint32_t s = (uint32_t)(row * (LDH * 2) + lc * 16);
            cp16(bh_s + s, Bh + g);
        }
        asm volatile("cp.async.commit_group;");
    };

    const uint32_t a_off = (uint32_t)((lane & 15) * (LDH * 2) + (lane >> 4) * 16);
    const uint32_t b_off = (uint32_t)(((lane & 7) + ((lane >> 4) << 3)) * (LDH * 2)
                                      + ((lane >> 3) & 1) * 16);

    float acc[2][8][4];
    #pragma unroll
    for (int i = 0; i < 2; ++i)
        #pragma unroll
        for (int j = 0; j < 8; ++j)
            #pragma unroll
            for (int q = 0; q < 4; ++q) acc[i][j][q] = 0.0f;

    load_stage(0, 0);
    load_stage(1, 1);
    load_stage(2, 2);

    for (int it = 0; it < KI; ++it) {
        asm volatile("cp.async.wait_group 2;");
        __syncthreads();

        const int buf = it - (it / NSTAGE) * NSTAGE;
        const uint32_t st = smb + (uint32_t)buf * STAGE_B;
        const uint32_t a_h = st + (uint32_t)(wm * 32) * (LDH * 2) + a_off;
        const uint32_t a_l = a_h + A_TERM_B;
        const uint32_t b_h = st + 2 * A_TERM_B + (uint32_t)(wn * 64) * (LDH * 2) + b_off;

        #pragma unroll
        for (int s = 0; s < 4; ++s) {                 // 4 k16-steps per BK=64
            const uint32_t koff = (uint32_t)(s << 5); // 16 halves = 32B

            uint32_t ah[2][4], al[2][4];
            #pragma unroll
            for (int mf = 0; mf < 2; ++mf) {
                const uint32_t moff = (uint32_t)(mf * 16 * (LDH * 2)) + koff;
                ldm_x4(ah[mf][0], ah[mf][1], ah[mf][2], ah[mf][3], a_h + moff);
                ldm_x4(al[mf][0], al[mf][1], al[mf][2], al[mf][3], a_l + moff);
            }
            uint32_t bh[8][2];
            #pragma unroll
            for (int np = 0; np < 4; ++np) {
                const uint32_t noff = (uint32_t)(np * 16 * (LDH * 2)) + koff;
                uint32_t r0, r1, r2, r3;
                ldm_x4(r0, r1, r2, r3, b_h + noff);
                bh[np*2][0] = r0; bh[np*2][1] = r1; bh[np*2+1][0] = r2; bh[np*2+1][1] = r3;
            }
            #pragma unroll
            for (int mf = 0; mf < 2; ++mf)
                #pragma unroll
                for (int nf = 0; nf < 8; ++nf)
                    mma16(acc[mf][nf], ah[mf], bh[nf][0], bh[nf][1]);
            #pragma unroll
            for (int mf = 0; mf < 2; ++mf)
                #pragma unroll
                for (int nf = 0; nf < 8; ++nf)
                    mma16(acc[mf][nf], al[mf], bh[nf][0], bh[nf][1]);
        }

        __syncthreads();
        const int nt = it + NSTAGE;
        if (nt < KI) load_stage(buf, nt);
        else         asm volatile("cp.async.commit_group;");
    }

    // ---- epilogue ----
    const bool hb = (bias != nullptr);
    const bool dosplit  = (Ch != nullptr) && (Cl != nullptr);
    const bool dosingle = (Ch != nullptr) && (Cl == nullptr);
    #pragma unroll
    for (int mf = 0; mf < 2; ++mf) {
        const int r0 = bm + wm * 32 + mf * 16 + (lane >> 2);
        #pragma unroll
        for (int nf = 0; nf < 8; ++nf) {
            const int col = bn + wn * 64 + nf * 8 + ((lane & 3) << 1);
            float v[4];
            v[0] = acc[mf][nf][0]; v[1] = acc[mf][nf][1];
            v[2] = acc[mf][nf][2]; v[3] = acc[mf][nf][3];
            if (hb) {
                const float bx = bias[col], by = bias[col + 1];
                v[0] += bx; v[1] += by; v[2] += bx; v[3] += by;
            }
            if (relu) {
                v[0] = fmaxf(v[0], 0.f); v[1] = fmaxf(v[1], 0.f);
                v[2] = fmaxf(v[2], 0.f); v[3] = fmaxf(v[3], 0.f);
            }
            const size_t o0 = (size_t)r0 * N + col;
            const size_t o1 = (size_t)(r0 + 8) * N + col;
            if (dosplit) {
                hf h[4], l[4];
                split_hf(v[0], h[0], l[0]); split_hf(v[1], h[1], l[1]);
                split_hf(v[2], h[2], l[2]); split_hf(v[3], h[3], l[3]);
                *reinterpret_cast<uint32_t*>(Ch + o0) = *reinterpret_cast<uint32_t*>(h);
                *reinterpret_cast<uint32_t*>(Cl + o0) = *reinterpret_cast<uint32_t*>(l);
                *reinterpret_cast<uint32_t*>(Ch + o1) = *reinterpret_cast<uint32_t*>(h + 2);
                *reinterpret_cast<uint32_t*>(Cl + o1) = *reinterpret_cast<uint32_t*>(l + 2);
            } else if (dosingle) {
                hf h[4];
                h[0] = __float2half_rn(v[0]); h[1] = __float2half_rn(v[1]);
                h[2] = __float2half_rn(v[2]); h[3] = __float2half_rn(v[3]);
                *reinterpret_cast<uint32_t*>(Ch + o0) = *reinterpret_cast<uint32_t*>(h);
                *reinterpret_cast<uint32_t*>(Ch + o1) = *reinterpret_cast<uint32_t*>(h + 2);
            } else {
                *reinterpret_cast<float2*>(C + o0) = make_float2(v[0], v[1]);
                *reinterpret_cast<float2*>(C + o1) = make_float2(v[2], v[3]);
            }
        }
    }
}

// ---------------- per-row: normalize (x2), logsumexp, picked, argmax --------
__global__ __launch_bounds__(256)
void row_reduce(const float* __restrict__ sim, const int* __restrict__ target,
                const float* __restrict__ temp_p,
                float* __restrict__ picked, int* __restrict__ correct) {
    const int row = blockIdx.x;
    const float* s = sim + (size_t)row * NT;

    __shared__ float sv[NT];
    __shared__ float red_f[256];
    __shared__ float red_m[256];
    __shared__ int   red_i[256];

    const int tid = threadIdx.x;

    float sumsq = 0.0f;
    float vmax = -INFINITY; int vidx = 0;
    for (int j = tid; j < NT; j += 256) {
        float v = s[j];
        sv[j] = v;
        sumsq += v * v;
        if (v > vmax) { vmax = v; vidx = j; }
    }
    red_f[tid] = sumsq; red_m[tid] = vmax; red_i[tid] = vidx;
    __syncthreads();
    for (int st = 128; st > 0; st >>= 1) {
        if (tid < st) {
            red_f[tid] += red_f[tid + st];
            float om = red_m[tid + st]; int oi = red_i[tid + st];
            if (om > red_m[tid] || (om == red_m[tid] && oi < red_i[tid])) {
                red_m[tid] = om; red_i[tid] = oi;
            }
        }
        __syncthreads();
    }
    const float c1 = sqrtf(red_f[0]);
    const int   amax = red_i[0];
    const float gmax = red_m[0];
    __syncthreads();

    float ss2 = 0.0f;
    const float inv_c1 = 1.0f / c1;
    for (int j = tid; j < NT; j += 256) {
        float z = sv[j] * inv_c1;
        sv[j] = z;
        ss2 += z * z;
    }
    red_f[tid] = ss2;
    __syncthreads();
    for (int st = 128; st > 0; st >>= 1) {
        if (tid < st) red_f[tid] += red_f[tid + st];
        __syncthreads();
    }
    const float c2 = sqrtf(red_f[0]);
    __syncthreads();

    const float temp = temp_p[0];
    const float invt = 1.0f / (c2 * temp);
    const float lmax = (gmax * inv_c1) * invt;

    float se = 0.0f;
    for (int j = tid; j < NT; j += 256)
        se += expf(sv[j] * invt - lmax);
    red_f[tid] = se;
    __syncthreads();
    for (int st = 128; st > 0; st >>= 1) {
        if (tid < st) red_f[tid] += red_f[tid + st];
        __syncthreads();
    }

    if (tid == 0) {
        const float lse = lmax + logf(red_f[0]);
        const int t = target[row];
        picked[row]  = sv[t] * invt - lse;
        correct[row] = (amax == t) ? 1 : 0;
    }
}

// ---------------- deterministic final reduce --------------------------------
__global__ __launch_bounds__(1024)
void finalize(const float* __restrict__ picked, const int* __restrict__ correct,
              float* __restrict__ out, int out_size) {
    __shared__ float sp[1024];
    __shared__ int   sc[1024];
    const int tid = threadIdx.x;
    float s = 0.0f; int c = 0;
    for (int i = tid; i < BB; i += 1024) { s += picked[i]; c += correct[i]; }
    sp[tid] = s; sc[tid] = c;
    __syncthreads();
    for (int st = 512; st > 0; st >>= 1) {
        if (tid < st) { sp[tid] += sp[tid + st]; sc[tid] += sc[tid + st]; }
        __syncthreads();
    }
    if (tid == 0) {
        out[0] = -sp[0] / (float)BB;
        if (out_size >= 2) out[1] = (float)sc[0];
    }
}

// ---------------- launch ----------------------------------------------------
#define SYM(v, s) cudaGetSymbolAddress((void**)&v, s)

extern "C" void kernel_launch(void* const* d_in, const int* in_sizes, int n_in,
                              void* d_out, int out_size) {
    const float* img  = (const float*)d_in[0];
    const float* txt  = (const float*)d_in[1];
    const int*   tgt  = (const int*)  d_in[2];
    const float* temp = (const float*)d_in[3];
    const float* Wi0 = (const float*)d_in[4];  const float* bi0 = (const float*)d_in[5];
    const float* Wi1 = (const float*)d_in[6];  const float* bi1 = (const float*)d_in[7];
    const float* Wi2 = (const float*)d_in[8];  const float* bi2 = (const float*)d_in[9];
    const float* Wt0 = (const float*)d_in[10]; const float* bt0 = (const float*)d_in[11];
    const float* Wt1 = (const float*)d_in[12]; const float* bt1 = (const float*)d_in[13];
    const float* Wt2 = (const float*)d_in[14]; const float* bt2 = (const float*)d_in[15];
    // d_in[16] = logit_scale : cancels under row L2-normalization, unused.
    float* out = (float*)d_out;

    hf *img_h, *img_l, *txtT_h, *txtT_l, *ht1_h, *ht1_l, *ht2_h, *ht2_l;
    hf *ptxt_h, *hi1_h, *hi1_l, *hi2_h, *hi2_l, *pimg_h, *pimg_l;
    hf *Wi0T, *Wi1T, *Wi2T, *Wt0T, *Wt1T, *Wt2T;
    float *sim, *picked; int *corr;
    SYM(img_h,  g_img_h);  SYM(img_l,  g_img_l);
    SYM(txtT_h, g_txtT_h); SYM(txtT_l, g_txtT_l);
    SYM(ht1_h,  g_ht1_h);  SYM(ht1_l,  g_ht1_l);
    SYM(ht2_h,  g_ht2_h);  SYM(ht2_l,  g_ht2_l);
    SYM(ptxt_h, g_ptxt_h);
    SYM(hi1_h,  g_hi1_h);  SYM(hi1_l,  g_hi1_l);
    SYM(hi2_h,  g_hi2_h);  SYM(hi2_l,  g_hi2_l);
    SYM(pimg_h, g_pimg_h); SYM(pimg_l, g_pimg_l);
    SYM(Wi0T, g_Wi0T); SYM(Wi1T, g_Wi1T); SYM(Wi2T, g_Wi2T);
    SYM(Wt0T, g_Wt0T); SYM(Wt1T, g_Wt1T); SYM(Wt2T, g_Wt2T);
    SYM(sim, g_sim); SYM(picked, g_picked); SYM(corr, g_correct);

    cudaFuncSetAttribute(gemm_mma, cudaFuncAttributeMaxDynamicSharedMemorySize, GEMM_SMEM);

    dim3 tb(32, 8);

    // pre-kernels: weights -> single fp16 transposed; txt -> split; img -> split
    transpose_split2_k<<<dim3(HH/32, DD/32, 2), tb>>>(Wi0, Wi0T, nullptr, Wt0, Wt0T, nullptr, DD, HH);
    transpose_split2_k<<<dim3(HH/32, HH/32, 2), tb>>>(Wi1, Wi1T, nullptr, Wt1, Wt1T, nullptr, HH, HH);
    transpose_split2_k<<<dim3(DD/32, HH/32, 2), tb>>>(Wi2, Wi2T, nullptr, Wt2, Wt2T, nullptr, HH, DD);
    transpose_split2_k<<<dim3(NT/32, DD/32, 1), tb>>>(txt, txtT_h, txtT_l, txt, txtT_h, txtT_l, DD, NT);
    split_k<<<256, 256>>>(img, img_h, img_l, (size_t)BB * DD / 4);

    // img MLP:  [BB,DD] -> [BB,HH] -> [BB,HH] -> [BB,DD]  (split outputs)
    gemm_mma<<<dim3(HH/256, BB/128), 512, GEMM_SMEM>>>(
        img_h, img_l, Wi0T, bi0, nullptr, hi1_h, hi1_l, BB, HH, DD, 1);
    gemm_mma<<<dim3(HH/256, BB/128), 512, GEMM_SMEM>>>(
        hi1_h, hi1_l, Wi1T, bi1, nullptr, hi2_h, hi2_l, BB, HH, HH, 1);
    gemm_mma<<<dim3(DD/256, BB/128), 512, GEMM_SMEM>>>(
        hi2_h, hi2_l, Wi2T, bi2, nullptr, pimg_h, pimg_l, BB, DD, HH, 0);

    // txt MLP:  [NT,DD] -> [NT,HH] -> [NT,HH] -> [NT,DD]
    gemm_mma<<<dim3(HH/256, NT/128), 512, GEMM_SMEM>>>(
        txtT_h, txtT_l, Wt0T, bt0, nullptr, ht1_h, ht1_l, NT, HH, DD, 1);
    gemm_mma<<<dim3(HH/256, NT/128), 512, GEMM_SMEM>>>(
        ht1_h, ht1_l, Wt1T, bt1, nullptr, ht2_h, ht2_l, NT, HH, HH, 1);
    gemm_mma<<<dim3(DD/256, NT/128), 512, GEMM_SMEM>>>(
        ht2_h, ht2_l, Wt2T, bt2, nullptr, ptxt_h, nullptr, NT, DD, HH, 0);   // single fp16 out

    // similarity: sim[BB, NT] = pimg @ ptxt^T  (plain fp32 output)
    gemm_mma<<<dim3(NT/256, BB/128), 512, GEMM_SMEM>>>(
        pimg_h, pimg_l, ptxt_h, nullptr, sim, nullptr, nullptr, BB, NT, DD, 0);

    // per-row normalize + log-softmax pick + argmax
    row_reduce<<<BB, 256>>>(sim, tgt, temp, picked, corr);

    // final deterministic reduction
    finalize<<<1, 1024>>>(picked, corr, out, out_size);
}

// round 8
// speedup vs baseline: 3.7226x; 1.0812x over previous
#include <cuda_runtime.h>
#include <cuda_fp16.h>
#include <math.h>
#include <stdint.h>

// Problem dims (fixed by the reference)
#define BB   16384   // batch (img rows)
#define DD   512     // feature dim
#define NT   4096    // n text
#define HH   1024    // hidden

typedef __half hf;

// ---------------- scratch (device globals; no allocs allowed) ----------------
__device__ hf g_img_h [ (size_t)BB * DD ], g_img_l [ (size_t)BB * DD ];
__device__ hf g_txtT_h[ (size_t)NT * DD ], g_txtT_l[ (size_t)NT * DD ];
__device__ hf g_ht1_h [ (size_t)NT * HH ], g_ht1_l [ (size_t)NT * HH ];
__device__ hf g_ht2_h [ (size_t)NT * HH ], g_ht2_l [ (size_t)NT * HH ];
__device__ hf g_ptxt_h[ (size_t)NT * DD ];                      // B of sim: single
__device__ hf g_hi1_h [ (size_t)BB * HH ], g_hi1_l [ (size_t)BB * HH ];
__device__ hf g_hi2_h [ (size_t)BB * HH ], g_hi2_l [ (size_t)BB * HH ];
__device__ hf g_pimg_h[ (size_t)BB * DD ], g_pimg_l[ (size_t)BB * DD ];
__device__ hf g_Wi0T  [ (size_t)HH * DD ];
__device__ hf g_Wi1T  [ (size_t)HH * HH ];
__device__ hf g_Wi2T  [ (size_t)DD * HH ];
__device__ hf g_Wt0T  [ (size_t)HH * DD ];
__device__ hf g_Wt1T  [ (size_t)HH * HH ];
__device__ hf g_Wt2T  [ (size_t)DD * HH ];
__device__ float g_sim  [ (size_t)BB * NT ];   // [BB, NT]  (256 MB)
__device__ float g_picked [ BB ];
__device__ int   g_correct[ BB ];

__device__ __forceinline__ void split_hf(float v, hf& h, hf& l) {
    h = __float2half_rn(v);
    l = __float2half_rn(v - __half2float(h));
}

// ---------------- elementwise split: in -> (hi, lo) fp16 ----------------
__global__ __launch_bounds__(256)
void split_k(const float* __restrict__ in, hf* __restrict__ hi,
             hf* __restrict__ lo, size_t n4) {
    size_t i = (size_t)blockIdx.x * 256 + threadIdx.x;
    size_t stride = (size_t)gridDim.x * 256;
    for (; i < n4; i += stride) {
        float4 v = reinterpret_cast<const float4*>(in)[i];
        hf h[4], l[4];
        split_hf(v.x, h[0], l[0]); split_hf(v.y, h[1], l[1]);
        split_hf(v.z, h[2], l[2]); split_hf(v.w, h[3], l[3]);
        reinterpret_cast<uint2*>(hi)[i] = *reinterpret_cast<uint2*>(h);
        reinterpret_cast<uint2*>(lo)[i] = *reinterpret_cast<uint2*>(l);
    }
}

// ------ batched transpose (+optional split): 7 tensors in ONE launch --------
// desc.lo == null -> single fp16 output; all dims are multiples of 32.
struct TDesc { const float* in; hf* hi; hf* lo; int R; int C; };
struct TP7   { TDesc d[7]; };

__global__ void transpose_multi_k(TP7 p) {
    const TDesc d = p.d[blockIdx.z];
    const int c0 = blockIdx.x * 32, r0 = blockIdx.y * 32;
    if (c0 >= d.C || r0 >= d.R) return;          // block-uniform
    __shared__ float t[32][33];
    const int c = c0 + threadIdx.x;
    #pragma unroll
    for (int i = 0; i < 32; i += 8) {
        int r = r0 + threadIdx.y + i;
        t[threadIdx.y + i][threadIdx.x] = d.in[(size_t)r * d.C + c];
    }
    __syncthreads();
    const int oc = r0 + threadIdx.x;
    #pragma unroll
    for (int i = 0; i < 32; i += 8) {
        int orow = c0 + threadIdx.y + i;
        float v = t[threadIdx.x][threadIdx.y + i];
        if (d.lo) {
            hf h, l; split_hf(v, h, l);
            d.hi[(size_t)orow * d.R + oc] = h;
            d.lo[(size_t)orow * d.R + oc] = l;
        } else {
            d.hi[(size_t)orow * d.R + oc] = __float2half_rn(v);
        }
    }
}

// ====== mma.sync FP16 GEMM  C[M,N] = A[M,K] * B[N,K]^T  (A 2-part, B 1-part) =
// Block 128x256, BK=64, 16 warps (32m x 64n warp tile), 3-stage cp.async,
// single __syncthreads per K-iter (loads issued before compute).

#define LDH 72                        // halves per smem row (64 + 8 pad) = 144B
#define A_TERM_B (128 * LDH * 2)      // 18432 B per A term
#define B_TERM_B (256 * LDH * 2)      // 36864 B
#define STAGE_B  (2 * A_TERM_B + B_TERM_B)   // 73728 B
#define NSTAGE   3
#define GEMM_SMEM (NSTAGE * STAGE_B)  // 221184 B

__device__ __forceinline__ uint32_t smem_u32(const void* p) {
    uint32_t a;
    asm("{ .reg .u64 t; cvta.to.shared.u64 t, %1; cvt.u32.u64 %0, t; }" : "=r"(a) : "l"(p));
    return a;
}
__device__ __forceinline__ void cp16(uint32_t dst, const void* src) {
    asm volatile("cp.async.cg.shared.global [%0], [%1], 16;" :: "r"(dst), "l"(src));
}
__device__ __forceinline__ void ldm_x4(uint32_t& r0, uint32_t& r1, uint32_t& r2,
                                       uint32_t& r3, uint32_t addr) {
    asm volatile("ldmatrix.sync.aligned.m8n8.x4.shared.b16 {%0,%1,%2,%3}, [%4];"
                 : "=r"(r0), "=r"(r1), "=r"(r2), "=r"(r3) : "r"(addr));
}
__device__ __forceinline__ void mma16(float* c, const uint32_t* a, uint32_t b0, uint32_t b1) {
    asm volatile(
        "mma.sync.aligned.m16n8k16.row.col.f32.f16.f16.f32 "
        "{%0,%1,%2,%3}, {%4,%5,%6,%7}, {%8,%9}, {%0,%1,%2,%3};"
        : "+f"(c[0]), "+f"(c[1]), "+f"(c[2]), "+f"(c[3])
        : "r"(a[0]), "r"(a[1]), "r"(a[2]), "r"(a[3]), "r"(b0), "r"(b1));
}

__global__ __launch_bounds__(512, 1)
void gemm_mma(const hf* __restrict__ Ah, const hf* __restrict__ Al,
              const hf* __restrict__ Bh,
              const float* __restrict__ bias,
              float* __restrict__ C,                     // fp32 output (may be null)
              hf* __restrict__ Ch, hf* __restrict__ Cl,  // fp16 output(s) (may be null)
              int M, int N, int K, int relu)
{
    extern __shared__ char smraw[];
    const uint32_t smb = smem_u32(smraw);

    const int tid  = threadIdx.x;
    const int lane = tid & 31;
    const int wid  = tid >> 5;        // 0..15
    const int wm   = wid & 3;         // 4 m-groups of 32 rows
    const int wn   = wid >> 2;        // 4 n-groups of 64 cols
    const int bm   = blockIdx.y * 128;
    const int bn   = blockIdx.x * 256;

    const int KI = K >> 6;            // K/64 tiles

    const int lr = tid >> 3;          // 0..63 row
    const int lc = tid & 7;           // 16B-chunk index (0..7)

    auto load_stage = [&](int buf, int it) {
        const int k0 = it << 6;
        const uint32_t st = smb + (uint32_t)buf * STAGE_B;
        const uint32_t ah_s = st;
        const uint32_t al_s = st + A_TERM_B;
        const uint32_t bh_s = st + 2 * A_TERM_B;
        #pragma unroll
        for (int p = 0; p < 2; ++p) {                 // A: 128 rows (h + l)
            const int row = lr + p * 64;
            const size_t g = (size_t)(bm + row) * K + k0 + lc * 8;
            const uint32_t s = (uint32_t)(row * (LDH * 2) + lc * 16);
            cp16(ah_s + s, Ah + g);
            cp16(al_s + s, Al + g);
        }
        #pragma unroll
        for (int p = 0; p < 4; ++p) {                 // B: 256 rows (h only)
            const int row = lr + p * 64;
            const size_t g = (size_t)(bn + row) * K + k0 + lc * 8;
            const uint32_t s = (uint32_t)(row * (LDH * 2) + lc * 16);
            cp16(bh_s + s, Bh + g);
        }
        asm volatile("cp.async.commit_group;");
    };

    const uint32_t a_off = (uint32_t)((lane & 15) * (LDH * 2) + (lane >> 4) * 16);
    const uint32_t b_off = (uint32_t)(((lane & 7) + ((lane >> 4) << 3)) * (LDH * 2)
                                      + ((lane >> 3) & 1) * 16);

    float acc[2][8][4];
    #pragma unroll
    for (int i = 0; i < 2; ++i)
        #pragma unroll
        for (int j = 0; j < 8; ++j)
            #pragma unroll
            for (int q = 0; q < 4; ++q) acc[i][j][q] = 0.0f;

    // prologue: stages 0,1 in flight; wait for stage 0
    load_stage(0, 0);
    load_stage(1, 1);
    asm volatile("cp.async.wait_group 1;");
    __syncthreads();

    for (int it = 0; it < KI; ++it) {
        // issue next stage FIRST (its buffer was freed by last iter's sync)
        const int nt = it + 2;
        if (nt < KI) load_stage(nt - (nt / NSTAGE) * NSTAGE, nt);
        else         asm volatile("cp.async.commit_group;");

        const int buf = it - (it / NSTAGE) * NSTAGE;
        const uint32_t st = smb + (uint32_t)buf * STAGE_B;
        const uint32_t a_h = st + (uint32_t)(wm * 32) * (LDH * 2) + a_off;
        const uint32_t a_l = a_h + A_TERM_B;
        const uint32_t b_h = st + 2 * A_TERM_B + (uint32_t)(wn * 64) * (LDH * 2) + b_off;

        #pragma unroll
        for (int s = 0; s < 4; ++s) {                 // 4 k16-steps per BK=64
            const uint32_t koff = (uint32_t)(s << 5); // 16 halves = 32B

            uint32_t ah[2][4], al[2][4];
            #pragma unroll
            for (int mf = 0; mf < 2; ++mf) {
                const uint32_t moff = (uint32_t)(mf * 16 * (LDH * 2)) + koff;
                ldm_x4(ah[mf][0], ah[mf][1], ah[mf][2], ah[mf][3], a_h + moff);
                ldm_x4(al[mf][0], al[mf][1], al[mf][2], al[mf][3], a_l + moff);
            }
            uint32_t bh[8][2];
            #pragma unroll
            for (int np = 0; np < 4; ++np) {
                const uint32_t noff = (uint32_t)(np * 16 * (LDH * 2)) + koff;
                uint32_t r0, r1, r2, r3;
                ldm_x4(r0, r1, r2, r3, b_h + noff);
                bh[np*2][0] = r0; bh[np*2][1] = r1; bh[np*2+1][0] = r2; bh[np*2+1][1] = r3;
            }
            #pragma unroll
            for (int mf = 0; mf < 2; ++mf)
                #pragma unroll
                for (int nf = 0; nf < 8; ++nf)
                    mma16(acc[mf][nf], ah[mf], bh[nf][0], bh[nf][1]);
            #pragma unroll
            for (int mf = 0; mf < 2; ++mf)
                #pragma unroll
                for (int nf = 0; nf < 8; ++nf)
                    mma16(acc[mf][nf], al[mf], bh[nf][0], bh[nf][1]);
        }

        // one barrier per iter: stage it+1 arrived, buffer (it%3) free for reuse
        asm volatile("cp.async.wait_group 1;");
        __syncthreads();
    }

    // ---- epilogue ----
    const bool hb = (bias != nullptr);
    const bool dosplit  = (Ch != nullptr) && (Cl != nullptr);
    const bool dosingle = (Ch != nullptr) && (Cl == nullptr);
    #pragma unroll
    for (int mf = 0; mf < 2; ++mf) {
        const int r0 = bm + wm * 32 + mf * 16 + (lane >> 2);
        #pragma unroll
        for (int nf = 0; nf < 8; ++nf) {
            const int col = bn + wn * 64 + nf * 8 + ((lane & 3) << 1);
            float v[4];
            v[0] = acc[mf][nf][0]; v[1] = acc[mf][nf][1];
            v[2] = acc[mf][nf][2]; v[3] = acc[mf][nf][3];
            if (hb) {
                const float bx = bias[col], by = bias[col + 1];
                v[0] += bx; v[1] += by; v[2] += bx; v[3] += by;
            }
            if (relu) {
                v[0] = fmaxf(v[0], 0.f); v[1] = fmaxf(v[1], 0.f);
                v[2] = fmaxf(v[2], 0.f); v[3] = fmaxf(v[3], 0.f);
            }
            const size_t o0 = (size_t)r0 * N + col;
            const size_t o1 = (size_t)(r0 + 8) * N + col;
            if (dosplit) {
                hf h[4], l[4];
                split_hf(v[0], h[0], l[0]); split_hf(v[1], h[1], l[1]);
                split_hf(v[2], h[2], l[2]); split_hf(v[3], h[3], l[3]);
                *reinterpret_cast<uint32_t*>(Ch + o0) = *reinterpret_cast<uint32_t*>(h);
                *reinterpret_cast<uint32_t*>(Cl + o0) = *reinterpret_cast<uint32_t*>(l);
                *reinterpret_cast<uint32_t*>(Ch + o1) = *reinterpret_cast<uint32_t*>(h + 2);
                *reinterpret_cast<uint32_t*>(Cl + o1) = *reinterpret_cast<uint32_t*>(l + 2);
            } else if (dosingle) {
                hf h[4];
                h[0] = __float2half_rn(v[0]); h[1] = __float2half_rn(v[1]);
                h[2] = __float2half_rn(v[2]); h[3] = __float2half_rn(v[3]);
                *reinterpret_cast<uint32_t*>(Ch + o0) = *reinterpret_cast<uint32_t*>(h);
                *reinterpret_cast<uint32_t*>(Ch + o1) = *reinterpret_cast<uint32_t*>(h + 2);
            } else {
                *reinterpret_cast<float2*>(C + o0) = make_float2(v[0], v[1]);
                *reinterpret_cast<float2*>(C + o1) = make_float2(v[2], v[3]);
            }
        }
    }
}

// ---------------- per-row: normalize (x2), logsumexp, picked, argmax --------
__global__ __launch_bounds__(256)
void row_reduce(const float* __restrict__ sim, const int* __restrict__ target,
                const float* __restrict__ temp_p,
                float* __restrict__ picked, int* __restrict__ correct) {
    const int row = blockIdx.x;
    const float* s = sim + (size_t)row * NT;

    __shared__ float sv[NT];
    __shared__ float red_f[256];
    __shared__ float red_m[256];
    __shared__ int   red_i[256];

    const int tid = threadIdx.x;

    float sumsq = 0.0f;
    float vmax = -INFINITY; int vidx = 0;
    for (int j = tid; j < NT; j += 256) {
        float v = s[j];
        sv[j] = v;
        sumsq += v * v;
        if (v > vmax) { vmax = v; vidx = j; }
    }
    red_f[tid] = sumsq; red_m[tid] = vmax; red_i[tid] = vidx;
    __syncthreads();
    for (int st = 128; st > 0; st >>= 1) {
        if (tid < st) {
            red_f[tid] += red_f[tid + st];
            float om = red_m[tid + st]; int oi = red_i[tid + st];
            if (om > red_m[tid] || (om == red_m[tid] && oi < red_i[tid])) {
                red_m[tid] = om; red_i[tid] = oi;
            }
        }
        __syncthreads();
    }
    const float c1 = sqrtf(red_f[0]);
    const int   amax = red_i[0];
    const float gmax = red_m[0];
    __syncthreads();

    float ss2 = 0.0f;
    const float inv_c1 = 1.0f / c1;
    for (int j = tid; j < NT; j += 256) {
        float z = sv[j] * inv_c1;
        sv[j] = z;
        ss2 += z * z;
    }
    red_f[tid] = ss2;
    __syncthreads();
    for (int st = 128; st > 0; st >>= 1) {
        if (tid < st) red_f[tid] += red_f[tid + st];
        __syncthreads();
    }
    const float c2 = sqrtf(red_f[0]);
    __syncthreads();

    const float temp = temp_p[0];
    const float invt = 1.0f / (c2 * temp);
    const float lmax = (gmax * inv_c1) * invt;

    float se = 0.0f;
    for (int j = tid; j < NT; j += 256)
        se += expf(sv[j] * invt - lmax);
    red_f[tid] = se;
    __syncthreads();
    for (int st = 128; st > 0; st >>= 1) {
        if (tid < st) red_f[tid] += red_f[tid + st];
        __syncthreads();
    }

    if (tid == 0) {
        const float lse = lmax + logf(red_f[0]);
        const int t = target[row];
        picked[row]  = sv[t] * invt - lse;
        correct[row] = (amax == t) ? 1 : 0;
    }
}

// ---------------- deterministic final reduce --------------------------------
__global__ __launch_bounds__(1024)
void finalize(const float* __restrict__ picked, const int* __restrict__ correct,
              float* __restrict__ out, int out_size) {
    __shared__ float sp[1024];
    __shared__ int   sc[1024];
    const int tid = threadIdx.x;
    float s = 0.0f; int c = 0;
    for (int i = tid; i < BB; i += 1024) { s += picked[i]; c += correct[i]; }
    sp[tid] = s; sc[tid] = c;
    __syncthreads();
    for (int st = 512; st > 0; st >>= 1) {
        if (tid < st) { sp[tid] += sp[tid + st]; sc[tid] += sc[tid + st]; }
        __syncthreads();
    }
    if (tid == 0) {
        out[0] = -sp[0] / (float)BB;
        if (out_size >= 2) out[1] = (float)sc[0];
    }
}

// ---------------- launch ----------------------------------------------------
#define SYM(v, s) cudaGetSymbolAddress((void**)&v, s)

extern "C" void kernel_launch(void* const* d_in, const int* in_sizes, int n_in,
                              void* d_out, int out_size) {
    const float* img  = (const float*)d_in[0];
    const float* txt  = (const float*)d_in[1];
    const int*   tgt  = (const int*)  d_in[2];
    const float* temp = (const float*)d_in[3];
    const float* Wi0 = (const float*)d_in[4];  const float* bi0 = (const float*)d_in[5];
    const float* Wi1 = (const float*)d_in[6];  const float* bi1 = (const float*)d_in[7];
    const float* Wi2 = (const float*)d_in[8];  const float* bi2 = (const float*)d_in[9];
    const float* Wt0 = (const float*)d_in[10]; const float* bt0 = (const float*)d_in[11];
    const float* Wt1 = (const float*)d_in[12]; const float* bt1 = (const float*)d_in[13];
    const float* Wt2 = (const float*)d_in[14]; const float* bt2 = (const float*)d_in[15];
    // d_in[16] = logit_scale : cancels under row L2-normalization, unused.
    float* out = (float*)d_out;

    hf *img_h, *img_l, *txtT_h, *txtT_l, *ht1_h, *ht1_l, *ht2_h, *ht2_l;
    hf *ptxt_h, *hi1_h, *hi1_l, *hi2_h, *hi2_l, *pimg_h, *pimg_l;
    hf *Wi0T, *Wi1T, *Wi2T, *Wt0T, *Wt1T, *Wt2T;
    float *sim, *picked; int *corr;
    SYM(img_h,  g_img_h);  SYM(img_l,  g_img_l);
    SYM(txtT_h, g_txtT_h); SYM(txtT_l, g_txtT_l);
    SYM(ht1_h,  g_ht1_h);  SYM(ht1_l,  g_ht1_l);
    SYM(ht2_h,  g_ht2_h);  SYM(ht2_l,  g_ht2_l);
    SYM(ptxt_h, g_ptxt_h);
    SYM(hi1_h,  g_hi1_h);  SYM(hi1_l,  g_hi1_l);
    SYM(hi2_h,  g_hi2_h);  SYM(hi2_l,  g_hi2_l);
    SYM(pimg_h, g_pimg_h); SYM(pimg_l, g_pimg_l);
    SYM(Wi0T, g_Wi0T); SYM(Wi1T, g_Wi1T); SYM(Wi2T, g_Wi2T);
    SYM(Wt0T, g_Wt0T); SYM(Wt1T, g_Wt1T); SYM(Wt2T, g_Wt2T);
    SYM(sim, g_sim); SYM(picked, g_picked); SYM(corr, g_correct);

    cudaFuncSetAttribute(gemm_mma, cudaFuncAttributeMaxDynamicSharedMemorySize, GEMM_SMEM);

    // one-time stream/event setup for the fork-join (host objects, no device mem)
    static cudaStream_t s_txt = nullptr;
    static cudaEvent_t  ev_fork = nullptr, ev_join = nullptr;
    static bool fork_ok = false;
    if (!s_txt) {
        fork_ok = (cudaStreamCreateWithFlags(&s_txt, cudaStreamNonBlocking) == cudaSuccess)
               && (cudaEventCreateWithFlags(&ev_fork, cudaEventDisableTiming) == cudaSuccess)
               && (cudaEventCreateWithFlags(&ev_join, cudaEventDisableTiming) == cudaSuccess);
    }

    // ---- pre-kernels (2 launches) ----
    TP7 tp;
    tp.d[0] = { Wi0, Wi0T,  nullptr, DD, HH };
    tp.d[1] = { Wi1, Wi1T,  nullptr, HH, HH };
    tp.d[2] = { Wi2, Wi2T,  nullptr, HH, DD };
    tp.d[3] = { Wt0, Wt0T,  nullptr, DD, HH };
    tp.d[4] = { Wt1, Wt1T,  nullptr, HH, HH };
    tp.d[5] = { Wt2, Wt2T,  nullptr, HH, DD };
    tp.d[6] = { txt, txtT_h, txtT_l, DD, NT };
    transpose_multi_k<<<dim3(NT/32, HH/32, 7), dim3(32, 8)>>>(tp);
    split_k<<<256, 256>>>(img, img_h, img_l, (size_t)BB * DD / 4);

    // ---- fork: txt MLP on side stream, img MLP on main stream ----
    cudaStream_t st = 0;
    if (fork_ok) {
        cudaEventRecord(ev_fork, 0);
        cudaStreamWaitEvent(s_txt, ev_fork, 0);
        st = s_txt;
    }
    gemm_mma<<<dim3(HH/256, NT/128), 512, GEMM_SMEM, st>>>(
        txtT_h, txtT_l, Wt0T, bt0, nullptr, ht1_h, ht1_l, NT, HH, DD, 1);
    gemm_mma<<<dim3(HH/256, NT/128), 512, GEMM_SMEM, st>>>(
        ht1_h, ht1_l, Wt1T, bt1, nullptr, ht2_h, ht2_l, NT, HH, HH, 1);
    gemm_mma<<<dim3(DD/256, NT/128), 512, GEMM_SMEM, st>>>(
        ht2_h, ht2_l, Wt2T, bt2, nullptr, ptxt_h, nullptr, NT, DD, HH, 0);
    if (fork_ok) cudaEventRecord(ev_join, s_txt);

    gemm_mma<<<dim3(HH/256, BB/128), 512, GEMM_SMEM>>>(
        img_h, img_l, Wi0T, bi0, nullptr, hi1_h, hi1_l, BB, HH, DD, 1);
    gemm_mma<<<dim3(HH/256, BB/128), 512, GEMM_SMEM>>>(
        hi1_h, hi1_l, Wi1T, bi1, nullptr, hi2_h, hi2_l, BB, HH, HH, 1);
    gemm_mma<<<dim3(DD/256, BB/128), 512, GEMM_SMEM>>>(
        hi2_h, hi2_l, Wi2T, bi2, nullptr, pimg_h, pimg_l, BB, DD, HH, 0);

    if (fork_ok) cudaStreamWaitEvent(0, ev_join, 0);   // join before sim

    // similarity: sim[BB, NT] = pimg @ ptxt^T  (plain fp32 output)
    gemm_mma<<<dim3(NT/256, BB/128), 512, GEMM_SMEM>>>(
        pimg_h, pimg_l, ptxt_h, nullptr, sim, nullptr, nullptr, BB, NT, DD, 0);

    // per-row normalize + log-softmax pick + argmax
    row_reduce<<<BB, 256>>>(sim, tgt, temp, picked, corr);

    // final deterministic reduction
    finalize<<<1, 1024>>>(picked, corr, out, out_size);
}

// round 9
// speedup vs baseline: 4.1334x; 1.1104x over previous
#include <cuda_runtime.h>
#include <cuda_fp16.h>
#include <math.h>
#include <stdint.h>

// Problem dims (fixed by the reference)
#define BB   16384   // batch (img rows)
#define DD   512     // feature dim
#define NT   4096    // n text
#define HH   1024    // hidden

typedef __half hf;

// ---------------- scratch (device globals; no allocs allowed) ----------------
__device__ hf g_img_h [ (size_t)BB * DD ], g_img_l [ (size_t)BB * DD ];
__device__ hf g_txtT_h[ (size_t)NT * DD ], g_txtT_l[ (size_t)NT * DD ];
__device__ hf g_ht1_h [ (size_t)NT * HH ], g_ht1_l [ (size_t)NT * HH ];
__device__ hf g_ht2_h [ (size_t)NT * HH ], g_ht2_l [ (size_t)NT * HH ];
__device__ hf g_ptxt_h[ (size_t)NT * DD ];                      // B of sim: single
__device__ hf g_hi1_h [ (size_t)BB * HH ], g_hi1_l [ (size_t)BB * HH ];
__device__ hf g_hi2_h [ (size_t)BB * HH ], g_hi2_l [ (size_t)BB * HH ];
__device__ hf g_pimg_h[ (size_t)BB * DD ], g_pimg_l[ (size_t)BB * DD ];
__device__ hf g_Wi0T  [ (size_t)HH * DD ];
__device__ hf g_Wi1T  [ (size_t)HH * HH ];
__device__ hf g_Wi2T  [ (size_t)DD * HH ];
__device__ hf g_Wt0T  [ (size_t)HH * DD ];
__device__ hf g_Wt1T  [ (size_t)HH * HH ];
__device__ hf g_Wt2T  [ (size_t)DD * HH ];
__device__ float g_sim  [ (size_t)BB * NT ];   // [BB, NT]  (256 MB)
__device__ float g_picked [ BB ];
__device__ int   g_correct[ BB ];

__device__ __forceinline__ void split_hf(float v, hf& h, hf& l) {
    h = __float2half_rn(v);
    l = __float2half_rn(v - __half2float(h));
}

// ---------------- elementwise split: in -> (hi, lo) fp16 ----------------
__global__ __launch_bounds__(256)
void split_k(const float* __restrict__ in, hf* __restrict__ hi,
             hf* __restrict__ lo, size_t n4) {
    size_t i = (size_t)blockIdx.x * 256 + threadIdx.x;
    size_t stride = (size_t)gridDim.x * 256;
    for (; i < n4; i += stride) {
        float4 v = reinterpret_cast<const float4*>(in)[i];
        hf h[4], l[4];
        split_hf(v.x, h[0], l[0]); split_hf(v.y, h[1], l[1]);
        split_hf(v.z, h[2], l[2]); split_hf(v.w, h[3], l[3]);
        reinterpret_cast<uint2*>(hi)[i] = *reinterpret_cast<uint2*>(h);
        reinterpret_cast<uint2*>(lo)[i] = *reinterpret_cast<uint2*>(l);
    }
}

// ------ batched transpose (+optional split): 7 tensors in ONE launch --------
struct TDesc { const float* in; hf* hi; hf* lo; int R; int C; };
struct TP7   { TDesc d[7]; };

__global__ void transpose_multi_k(TP7 p) {
    const TDesc d = p.d[blockIdx.z];
    const int c0 = blockIdx.x * 32, r0 = blockIdx.y * 32;
    if (c0 >= d.C || r0 >= d.R) return;          // block-uniform
    __shared__ float t[32][33];
    const int c = c0 + threadIdx.x;
    #pragma unroll
    for (int i = 0; i < 32; i += 8) {
        int r = r0 + threadIdx.y + i;
        t[threadIdx.y + i][threadIdx.x] = d.in[(size_t)r * d.C + c];
    }
    __syncthreads();
    const int oc = r0 + threadIdx.x;
    #pragma unroll
    for (int i = 0; i < 32; i += 8) {
        int orow = c0 + threadIdx.y + i;
        float v = t[threadIdx.x][threadIdx.y + i];
        if (d.lo) {
            hf h, l; split_hf(v, h, l);
            d.hi[(size_t)orow * d.R + oc] = h;
            d.lo[(size_t)orow * d.R + oc] = l;
        } else {
            d.hi[(size_t)orow * d.R + oc] = __float2half_rn(v);
        }
    }
}

// ====== mma.sync FP16 GEMM  C[M,N] = A[M,K] * B[N,K]^T  (A 2-part, B 1-part) =
// Block 128x128, BK=64, 8 warps (32m x 64n warp tile), 2-stage cp.async,
// 2 CTAs per SM for barrier/latency overlap.

#define LDH 72                        // halves per smem row (64 + 8 pad) = 144B
#define A_TERM_B (128 * LDH * 2)      // 18432 B per A term
#define B_TERM_B (128 * LDH * 2)      // 18432 B
#define STAGE_B  (2 * A_TERM_B + B_TERM_B)   // 55296 B
#define NSTAGE   2
#define GEMM_SMEM (NSTAGE * STAGE_B)  // 110592 B -> 2 CTAs/SM

__device__ __forceinline__ uint32_t smem_u32(const void* p) {
    uint32_t a;
    asm("{ .reg .u64 t; cvta.to.shared.u64 t, %1; cvt.u32.u64 %0, t; }" : "=r"(a) : "l"(p));
    return a;
}
__device__ __forceinline__ void cp16(uint32_t dst, const void* src) {
    asm volatile("cp.async.cg.shared.global [%0], [%1], 16;" :: "r"(dst), "l"(src));
}
__device__ __forceinline__ void ldm_x4(uint32_t& r0, uint32_t& r1, uint32_t& r2,
                                       uint32_t& r3, uint32_t addr) {
    asm volatile("ldmatrix.sync.aligned.m8n8.x4.shared.b16 {%0,%1,%2,%3}, [%4];"
                 : "=r"(r0), "=r"(r1), "=r"(r2), "=r"(r3) : "r"(addr));
}
__device__ __forceinline__ void mma16(float* c, const uint32_t* a, uint32_t b0, uint32_t b1) {
    asm volatile(
        "mma.sync.aligned.m16n8k16.row.col.f32.f16.f16.f32 "
        "{%0,%1,%2,%3}, {%4,%5,%6,%7}, {%8,%9}, {%0,%1,%2,%3};"
        : "+f"(c[0]), "+f"(c[1]), "+f"(c[2]), "+f"(c[3])
        : "r"(a[0]), "r"(a[1]), "r"(a[2]), "r"(a[3]), "r"(b0), "r"(b1));
}

__global__ __launch_bounds__(256, 2)
void gemm_mma(const hf* __restrict__ Ah, const hf* __restrict__ Al,
              const hf* __restrict__ Bh,
              const float* __restrict__ bias,
              float* __restrict__ C,                     // fp32 output (may be null)
              hf* __restrict__ Ch, hf* __restrict__ Cl,  // fp16 output(s) (may be null)
              int M, int N, int K, int relu)
{
    extern __shared__ char smraw[];
    const uint32_t smb = smem_u32(smraw);

    const int tid  = threadIdx.x;
    const int lane = tid & 31;
    const int wid  = tid >> 5;        // 0..7
    const int wm   = wid & 3;         // 4 m-groups of 32 rows
    const int wn   = wid >> 2;        // 2 n-groups of 64 cols
    const int bm   = blockIdx.y * 128;
    const int bn   = blockIdx.x * 128;

    const int KI = K >> 6;            // K/64 tiles

    const int lr = tid >> 3;          // 0..31 row base
    const int lc = tid & 7;           // 16B-chunk index (0..7)

    auto load_stage = [&](int buf, int it) {
        const int k0 = it << 6;
        const uint32_t st = smb + (uint32_t)buf * STAGE_B;
        const uint32_t ah_s = st;
        const uint32_t al_s = st + A_TERM_B;
        const uint32_t bh_s = st + 2 * A_TERM_B;
        #pragma unroll
        for (int p = 0; p < 4; ++p) {                 // A: 128 rows (h + l)
            const int row = lr + p * 32;
            const size_t g = (size_t)(bm + row) * K + k0 + lc * 8;
            const uint32_t s = (uint32_t)(row * (LDH * 2) + lc * 16);
            cp16(ah_s + s, Ah + g);
            cp16(al_s + s, Al + g);
        }
        #pragma unroll
        for (int p = 0; p < 4; ++p) {                 // B: 128 rows (h only)
            const int row = lr + p * 32;
            const size_t g = (size_t)(bn + row) * K + k0 + lc * 8;
            const uint32_t s = (uint32_t)(row * (LDH * 2) + lc * 16);
            cp16(bh_s + s, Bh + g);
        }
        asm volatile("cp.async.commit_group;");
    };

    const uint32_t a_off = (uint32_t)((lane & 15) * (LDH * 2) + (lane >> 4) * 16);
    const uint32_t b_off = (uint32_t)(((lane & 7) + ((lane >> 4) << 3)) * (LDH * 2)
                                      + ((lane >> 3) & 1) * 16);

    float acc[2][8][4];
    #pragma unroll
    for (int i = 0; i < 2; ++i)
        #pragma unroll
        for (int j = 0; j < 8; ++j)
            #pragma unroll
            for (int q = 0; q < 4; ++q) acc[i][j][q] = 0.0f;

    load_stage(0, 0);
    load_stage(1, 1);

    for (int it = 0; it < KI; ++it) {
        asm volatile("cp.async.wait_group 1;");       // stage `it` resident
        __syncthreads();

        const int buf = it & 1;
        const uint32_t st = smb + (uint32_t)buf * STAGE_B;
        const uint32_t a_h = st + (uint32_t)(wm * 32) * (LDH * 2) + a_off;
        const uint32_t a_l = a_h + A_TERM_B;
        const uint32_t b_h = st + 2 * A_TERM_B + (uint32_t)(wn * 64) * (LDH * 2) + b_off;

        #pragma unroll
        for (int s = 0; s < 4; ++s) {                 // 4 k16-steps per BK=64
            const uint32_t koff = (uint32_t)(s << 5); // 16 halves = 32B

            uint32_t ah[2][4], al[2][4];
            #pragma unroll
            for (int mf = 0; mf < 2; ++mf) {
                const uint32_t moff = (uint32_t)(mf * 16 * (LDH * 2)) + koff;
                ldm_x4(ah[mf][0], ah[mf][1], ah[mf][2], ah[mf][3], a_h + moff);
                ldm_x4(al[mf][0], al[mf][1], al[mf][2], al[mf][3], a_l + moff);
            }
            uint32_t bh[8][2];
            #pragma unroll
            for (int np = 0; np < 4; ++np) {
                const uint32_t noff = (uint32_t)(np * 16 * (LDH * 2)) + koff;
                uint32_t r0, r1, r2, r3;
                ldm_x4(r0, r1, r2, r3, b_h + noff);
                bh[np*2][0] = r0; bh[np*2][1] = r1; bh[np*2+1][0] = r2; bh[np*2+1][1] = r3;
            }
            #pragma unroll
            for (int mf = 0; mf < 2; ++mf)
                #pragma unroll
                for (int nf = 0; nf < 8; ++nf)
                    mma16(acc[mf][nf], ah[mf], bh[nf][0], bh[nf][1]);
            #pragma unroll
            for (int mf = 0; mf < 2; ++mf)
                #pragma unroll
                for (int nf = 0; nf < 8; ++nf)
                    mma16(acc[mf][nf], al[mf], bh[nf][0], bh[nf][1]);
        }

        __syncthreads();                              // done reading buf
        const int nt = it + 2;
        if (nt < KI) load_stage(buf, nt);
        else         asm volatile("cp.async.commit_group;");
    }

    // ---- epilogue ----
    const bool hb = (bias != nullptr);
    const bool dosplit  = (Ch != nullptr) && (Cl != nullptr);
    const bool dosingle = (Ch != nullptr) && (Cl == nullptr);
    #pragma unroll
    for (int mf = 0; mf < 2; ++mf) {
        const int r0 = bm + wm * 32 + mf * 16 + (lane >> 2);
        #pragma unroll
        for (int nf = 0; nf < 8; ++nf) {
            const int col = bn + wn * 64 + nf * 8 + ((lane & 3) << 1);
            float v[4];
            v[0] = acc[mf][nf][0]; v[1] = acc[mf][nf][1];
            v[2] = acc[mf][nf][2]; v[3] = acc[mf][nf][3];
            if (hb) {
                const float bx = bias[col], by = bias[col + 1];
                v[0] += bx; v[1] += by; v[2] += bx; v[3] += by;
            }
            if (relu) {
                v[0] = fmaxf(v[0], 0.f); v[1] = fmaxf(v[1], 0.f);
                v[2] = fmaxf(v[2], 0.f); v[3] = fmaxf(v[3], 0.f);
            }
            const size_t o0 = (size_t)r0 * N + col;
            const size_t o1 = (size_t)(r0 + 8) * N + col;
            if (dosplit) {
                hf h[4], l[4];
                split_hf(v[0], h[0], l[0]); split_hf(v[1], h[1], l[1]);
                split_hf(v[2], h[2], l[2]); split_hf(v[3], h[3], l[3]);
                *reinterpret_cast<uint32_t*>(Ch + o0) = *reinterpret_cast<uint32_t*>(h);
                *reinterpret_cast<uint32_t*>(Cl + o0) = *reinterpret_cast<uint32_t*>(l);
                *reinterpret_cast<uint32_t*>(Ch + o1) = *reinterpret_cast<uint32_t*>(h + 2);
                *reinterpret_cast<uint32_t*>(Cl + o1) = *reinterpret_cast<uint32_t*>(l + 2);
            } else if (dosingle) {
                hf h[4];
                h[0] = __float2half_rn(v[0]); h[1] = __float2half_rn(v[1]);
                h[2] = __float2half_rn(v[2]); h[3] = __float2half_rn(v[3]);
                *reinterpret_cast<uint32_t*>(Ch + o0) = *reinterpret_cast<uint32_t*>(h);
                *reinterpret_cast<uint32_t*>(Ch + o1) = *reinterpret_cast<uint32_t*>(h + 2);
            } else {
                *reinterpret_cast<float2*>(C + o0) = make_float2(v[0], v[1]);
                *reinterpret_cast<float2*>(C + o1) = make_float2(v[2], v[3]);
            }
        }
    }
}

// ---------------- per-row: normalize (x2), logsumexp, picked, argmax --------
__global__ __launch_bounds__(256)
void row_reduce(const float* __restrict__ sim, const int* __restrict__ target,
                const float* __restrict__ temp_p,
                float* __restrict__ picked, int* __restrict__ correct) {
    const int row = blockIdx.x;
    const float* s = sim + (size_t)row * NT;

    __shared__ float sv[NT];
    __shared__ float red_f[256];
    __shared__ float red_m[256];
    __shared__ int   red_i[256];

    const int tid = threadIdx.x;

    float sumsq = 0.0f;
    float vmax = -INFINITY; int vidx = 0;
    for (int j = tid; j < NT; j += 256) {
        float v = s[j];
        sv[j] = v;
        sumsq += v * v;
        if (v > vmax) { vmax = v; vidx = j; }
    }
    red_f[tid] = sumsq; red_m[tid] = vmax; red_i[tid] = vidx;
    __syncthreads();
    for (int st = 128; st > 0; st >>= 1) {
        if (tid < st) {
            red_f[tid] += red_f[tid + st];
            float om = red_m[tid + st]; int oi = red_i[tid + st];
            if (om > red_m[tid] || (om == red_m[tid] && oi < red_i[tid])) {
                red_m[tid] = om; red_i[tid] = oi;
            }
        }
        __syncthreads();
    }
    const float c1 = sqrtf(red_f[0]);
    const int   amax = red_i[0];
    const float gmax = red_m[0];
    __syncthreads();

    float ss2 = 0.0f;
    const float inv_c1 = 1.0f / c1;
    for (int j = tid; j < NT; j += 256) {
        float z = sv[j] * inv_c1;
        sv[j] = z;
        ss2 += z * z;
    }
    red_f[tid] = ss2;
    __syncthreads();
    for (int st = 128; st > 0; st >>= 1) {
        if (tid < st) red_f[tid] += red_f[tid + st];
        __syncthreads();
    }
    const float c2 = sqrtf(red_f[0]);
    __syncthreads();

    const float temp = temp_p[0];
    const float invt = 1.0f / (c2 * temp);
    const float lmax = (gmax * inv_c1) * invt;

    float se = 0.0f;
    for (int j = tid; j < NT; j += 256)
        se += expf(sv[j] * invt - lmax);
    red_f[tid] = se;
    __syncthreads();
    for (int st = 128; st > 0; st >>= 1) {
        if (tid < st) red_f[tid] += red_f[tid + st];
        __syncthreads();
    }

    if (tid == 0) {
        const float lse = lmax + logf(red_f[0]);
        const int t = target[row];
        picked[row]  = sv[t] * invt - lse;
        correct[row] = (amax == t) ? 1 : 0;
    }
}

// ---------------- deterministic final reduce --------------------------------
__global__ __launch_bounds__(1024)
void finalize(const float* __restrict__ picked, const int* __restrict__ correct,
              float* __restrict__ out, int out_size) {
    __shared__ float sp[1024];
    __shared__ int   sc[1024];
    const int tid = threadIdx.x;
    float s = 0.0f; int c = 0;
    for (int i = tid; i < BB; i += 1024) { s += picked[i]; c += correct[i]; }
    sp[tid] = s; sc[tid] = c;
    __syncthreads();
    for (int st = 512; st > 0; st >>= 1) {
        if (tid < st) { sp[tid] += sp[tid + st]; sc[tid] += sc[tid + st]; }
        __syncthreads();
    }
    if (tid == 0) {
        out[0] = -sp[0] / (float)BB;
        if (out_size >= 2) out[1] = (float)sc[0];
    }
}

// ---------------- launch ----------------------------------------------------
#define SYM(v, s) cudaGetSymbolAddress((void**)&v, s)

extern "C" void kernel_launch(void* const* d_in, const int* in_sizes, int n_in,
                              void* d_out, int out_size) {
    const float* img  = (const float*)d_in[0];
    const float* txt  = (const float*)d_in[1];
    const int*   tgt  = (const int*)  d_in[2];
    const float* temp = (const float*)d_in[3];
    const float* Wi0 = (const float*)d_in[4];  const float* bi0 = (const float*)d_in[5];
    const float* Wi1 = (const float*)d_in[6];  const float* bi1 = (const float*)d_in[7];
    const float* Wi2 = (const float*)d_in[8];  const float* bi2 = (const float*)d_in[9];
    const float* Wt0 = (const float*)d_in[10]; const float* bt0 = (const float*)d_in[11];
    const float* Wt1 = (const float*)d_in[12]; const float* bt1 = (const float*)d_in[13];
    const float* Wt2 = (const float*)d_in[14]; const float* bt2 = (const float*)d_in[15];
    // d_in[16] = logit_scale : cancels under row L2-normalization, unused.
    float* out = (float*)d_out;

    hf *img_h, *img_l, *txtT_h, *txtT_l, *ht1_h, *ht1_l, *ht2_h, *ht2_l;
    hf *ptxt_h, *hi1_h, *hi1_l, *hi2_h, *hi2_l, *pimg_h, *pimg_l;
    hf *Wi0T, *Wi1T, *Wi2T, *Wt0T, *Wt1T, *Wt2T;
    float *sim, *picked; int *corr;
    SYM(img_h,  g_img_h);  SYM(img_l,  g_img_l);
    SYM(txtT_h, g_txtT_h); SYM(txtT_l, g_txtT_l);
    SYM(ht1_h,  g_ht1_h);  SYM(ht1_l,  g_ht1_l);
    SYM(ht2_h,  g_ht2_h);  SYM(ht2_l,  g_ht2_l);
    SYM(ptxt_h, g_ptxt_h);
    SYM(hi1_h,  g_hi1_h);  SYM(hi1_l,  g_hi1_l);
    SYM(hi2_h,  g_hi2_h);  SYM(hi2_l,  g_hi2_l);
    SYM(pimg_h, g_pimg_h); SYM(pimg_l, g_pimg_l);
    SYM(Wi0T, g_Wi0T); SYM(Wi1T, g_Wi1T); SYM(Wi2T, g_Wi2T);
    SYM(Wt0T, g_Wt0T); SYM(Wt1T, g_Wt1T); SYM(Wt2T, g_Wt2T);
    SYM(sim, g_sim); SYM(picked, g_picked); SYM(corr, g_correct);

    cudaFuncSetAttribute(gemm_mma, cudaFuncAttributeMaxDynamicSharedMemorySize, GEMM_SMEM);

    static cudaStream_t s_txt = nullptr;
    static cudaEvent_t  ev_fork = nullptr, ev_join = nullptr;
    static bool fork_ok = false;
    if (!s_txt) {
        fork_ok = (cudaStreamCreateWithFlags(&s_txt, cudaStreamNonBlocking) == cudaSuccess)
               && (cudaEventCreateWithFlags(&ev_fork, cudaEventDisableTiming) == cudaSuccess)
               && (cudaEventCreateWithFlags(&ev_join, cudaEventDisableTiming) == cudaSuccess);
    }

    // ---- pre-kernels (2 launches) ----
    TP7 tp;
    tp.d[0] = { Wi0, Wi0T,  nullptr, DD, HH };
    tp.d[1] = { Wi1, Wi1T,  nullptr, HH, HH };
    tp.d[2] = { Wi2, Wi2T,  nullptr, HH, DD };
    tp.d[3] = { Wt0, Wt0T,  nullptr, DD, HH };
    tp.d[4] = { Wt1, Wt1T,  nullptr, HH, HH };
    tp.d[5] = { Wt2, Wt2T,  nullptr, HH, DD };
    tp.d[6] = { txt, txtT_h, txtT_l, DD, NT };
    transpose_multi_k<<<dim3(NT/32, HH/32, 7), dim3(32, 8)>>>(tp);
    split_k<<<256, 256>>>(img, img_h, img_l, (size_t)BB * DD / 4);

    // ---- fork: txt MLP on side stream, img MLP on main stream ----
    cudaStream_t st = 0;
    if (fork_ok) {
        cudaEventRecord(ev_fork, 0);
        cudaStreamWaitEvent(s_txt, ev_fork, 0);
        st = s_txt;
    }
    gemm_mma<<<dim3(HH/128, NT/128), 256, GEMM_SMEM, st>>>(
        txtT_h, txtT_l, Wt0T, bt0, nullptr, ht1_h, ht1_l, NT, HH, DD, 1);
    gemm_mma<<<dim3(HH/128, NT/128), 256, GEMM_SMEM, st>>>(
        ht1_h, ht1_l, Wt1T, bt1, nullptr, ht2_h, ht2_l, NT, HH, HH, 1);
    gemm_mma<<<dim3(DD/128, NT/128), 256, GEMM_SMEM, st>>>(
        ht2_h, ht2_l, Wt2T, bt2, nullptr, ptxt_h, nullptr, NT, DD, HH, 0);
    if (fork_ok) cudaEventRecord(ev_join, s_txt);

    gemm_mma<<<dim3(HH/128, BB/128), 256, GEMM_SMEM>>>(
        img_h, img_l, Wi0T, bi0, nullptr, hi1_h, hi1_l, BB, HH, DD, 1);
    gemm_mma<<<dim3(HH/128, BB/128), 256, GEMM_SMEM>>>(
        hi1_h, hi1_l, Wi1T, bi1, nullptr, hi2_h, hi2_l, BB, HH, HH, 1);
    gemm_mma<<<dim3(DD/128, BB/128), 256, GEMM_SMEM>>>(
        hi2_h, hi2_l, Wi2T, bi2, nullptr, pimg_h, pimg_l, BB, DD, HH, 0);

    if (fork_ok) cudaStreamWaitEvent(0, ev_join, 0);   // join before sim

    // similarity: sim[BB, NT] = pimg @ ptxt^T  (plain fp32 output)
    gemm_mma<<<dim3(NT/128, BB/128), 256, GEMM_SMEM>>>(
        pimg_h, pimg_l, ptxt_h, nullptr, sim, nullptr, nullptr, BB, NT, DD, 0);

    // per-row normalize + log-softmax pick + argmax
    row_reduce<<<BB, 256>>>(sim, tgt, temp, picked, corr);

    // final deterministic reduction
    finalize<<<1, 1024>>>(picked, corr, out, out_size);
}